// round 2
// baseline (speedup 1.0000x reference)
#include <cuda_runtime.h>

// Problem constants
#define BB 4
#define TT 16
#define NN 512
#define FF 5
#define HH 64
#define SS 2048      // B*N sequences
#define RR 824
#define GG 256       // 4*H gates
#define R4 (RR/4)    // 206 float4 per relation row

#define NLSTM SS                 // 2048 lstm blocks
#define NRELW (NN*NN/8)          // 32768 relw blocks (8 warps x 1 pair each)
#define NTOT  (NLSTM + NRELW)    // 34816 = 17 * 2048  (1:16 interleave)

// Scratch (device globals; no allocation allowed)
__device__ float g_relw[NN * NN];   // leaky(enc . fc1_w + fc1_b)  [n,m]
__device__ float g_tail[SS];        // leaky(out . fc3_w + fc3_b)
__device__ float g_q[SS];           // out . pred_w[64:128]
__device__ float g_p0[SS];          // out . pred_w[0:64]

__device__ __forceinline__ float leaky(float v) { return v > 0.f ? v : 0.01f * v; }
__device__ __forceinline__ float sigm(float v)  { return 1.f / (1.f + expf(-v)); }

// ---------------------------------------------------------------------------
// Fused kernel: role by blockIdx, interleaved 1 lstm : 16 relw so both the
// FMA pipe (lstm) and DRAM (relw) are busy in every scheduling wave.
// ---------------------------------------------------------------------------
__global__ __launch_bounds__(256, 2) void fused_kernel(
    const float* __restrict__ x,
    const float* __restrict__ enc,
    const float* __restrict__ Wih_f, const float* __restrict__ Whh_f,
    const float* __restrict__ bih_f, const float* __restrict__ bhh_f,
    const float* __restrict__ Wih_b,
    const float* __restrict__ bih_b, const float* __restrict__ bhh_b,
    const float* __restrict__ fc0_w, const float* __restrict__ fc0_b,
    const float* __restrict__ fc1_w, const float* __restrict__ fc1_b,
    const float* __restrict__ fc3_w, const float* __restrict__ fc3_b,
    const float* __restrict__ pred_w)
{
    int bid = blockIdx.x;
    int tid = threadIdx.x;

    if (bid % 17 != 0) {
        // =================== relw role: one warp per (n,m) pair ============
        __shared__ float4 wsm[R4];
        const float4* w4g = (const float4*)fc1_w;
        for (int i = tid; i < R4; i += 256) wsm[i] = w4g[i];
        __syncthreads();

        int rid = bid - bid / 17 - 1;              // 0 .. NRELW-1
        int warp = tid >> 5, lane = tid & 31;
        int pair = rid * 8 + warp;                 // < 262144
        const float4* row = (const float4*)enc + (long long)pair * R4;

        // 206 = 6*32 + 14 : 6 full unrolled strides + predicated tail.
        float4 v0 = __ldcs(row + lane);
        float4 v1 = __ldcs(row + lane + 32);
        float4 v2 = __ldcs(row + lane + 64);
        float4 v3 = __ldcs(row + lane + 96);
        float4 v4 = __ldcs(row + lane + 128);
        float4 v5 = __ldcs(row + lane + 160);
        float4 v6 = (lane < 14) ? __ldcs(row + lane + 192)
                                : make_float4(0.f, 0.f, 0.f, 0.f);

        float acc = 0.f;
        float4 w;
        w = wsm[lane];       acc += v0.x*w.x + v0.y*w.y + v0.z*w.z + v0.w*w.w;
        w = wsm[lane + 32];  acc += v1.x*w.x + v1.y*w.y + v1.z*w.z + v1.w*w.w;
        w = wsm[lane + 64];  acc += v2.x*w.x + v2.y*w.y + v2.z*w.z + v2.w*w.w;
        w = wsm[lane + 96];  acc += v3.x*w.x + v3.y*w.y + v3.z*w.z + v3.w*w.w;
        w = wsm[lane + 128]; acc += v4.x*w.x + v4.y*w.y + v4.z*w.z + v4.w*w.w;
        w = wsm[lane + 160]; acc += v5.x*w.x + v5.y*w.y + v5.z*w.z + v5.w*w.w;
        if (lane < 14) {
            w = wsm[lane + 192];
            acc += v6.x*w.x + v6.y*w.y + v6.z*w.z + v6.w*w.w;
        }
#pragma unroll
        for (int o = 16; o; o >>= 1) acc += __shfl_xor_sync(0xffffffffu, acc, o);
        if (lane == 0) g_relw[pair] = leaky(acc + fc1_b[0]);
        return;
    }

    // ===================== lstm role: one CTA per sequence =================
    __shared__ float xs[TT * FF];                      // 80
    __shared__ __align__(16) float sh_h[HH];           // hidden state
    __shared__ float arr[GG];                          // activated gates
    __shared__ __align__(16) float last[2 * HH];       // [h_fwd_last, h_bwd_first]
    __shared__ float out_sm[HH];

    int s = bid / 17;                                  // sequence id
    int b = s >> 9, n = s & (NN - 1);
    int g = tid;                                       // gate index 0..255

    // Load the 16x5 input slice: new_x[s,t,f] = x[b,t,n,f]
    if (tid < TT * FF) {
        int t = tid / FF, f = tid - t * FF;
        xs[tid] = x[((b * TT + t) * NN + n) * FF + f];
    }
    if (tid < HH) sh_h[tid] = 0.f;

    // Per-thread forward weights (Whh row register-resident)
    float wh[HH];
#pragma unroll
    for (int j = 0; j < HH / 4; j++) {
        float4 v = ((const float4*)Whh_f)[g * (HH / 4) + j];
        wh[4*j] = v.x; wh[4*j+1] = v.y; wh[4*j+2] = v.z; wh[4*j+3] = v.w;
    }
    float bf = bih_f[g] + bhh_f[g];
    float wf0 = Wih_f[g*FF], wf1 = Wih_f[g*FF+1], wf2 = Wih_f[g*FF+2],
          wf3 = Wih_f[g*FF+3], wf4 = Wih_f[g*FF+4];
    __syncthreads();

    // Hoist x @ Wih out of the recurrence: xb[t] = bf + x_t . wf
    float xb[TT];
#pragma unroll
    for (int t = 0; t < TT; t++) {
        const float* xt = xs + t * FF;
        xb[t] = bf + xt[0]*wf0 + xt[1]*wf1 + xt[2]*wf2 + xt[3]*wf3 + xt[4]*wf4;
    }

    float c = 0.f;
    int gtype = g >> 6;   // 0=i 1=f 2=g 3=o  (per-warp uniform)

    // ---- forward recurrence, 16 steps; float4 LDS + 4 accumulators ----
    const float4* h4 = (const float4*)sh_h;
    for (int t = 0; t < TT; t++) {
        float a0 = xb[t], a1 = 0.f, a2 = 0.f, a3 = 0.f;
#pragma unroll
        for (int k = 0; k < HH / 4; k++) {
            float4 hv = h4[k];
            a0 += hv.x * wh[4*k];
            a1 += hv.y * wh[4*k+1];
            a2 += hv.z * wh[4*k+2];
            a3 += hv.w * wh[4*k+3];
        }
        float acc = (a0 + a1) + (a2 + a3);
        arr[g] = (gtype == 2) ? tanhf(acc) : sigm(acc);
        __syncthreads();
        if (tid < HH) {
            float gi = arr[tid], gf = arr[HH + tid];
            float gc = arr[2*HH + tid], go = arr[3*HH + tid];
            c = gf * c + gi * gc;
            sh_h[tid] = go * tanhf(c);
        }
        __syncthreads();
    }
    if (tid < HH) last[tid] = sh_h[tid];

    // ---- backward LSTM: only hs_b[0] is consumed -> one step, zero state ----
    {
        const float* xt = xs + (TT - 1) * FF;
        float acc = bih_b[g] + bhh_b[g];
#pragma unroll
        for (int j = 0; j < FF; j++) acc += xt[j] * Wih_b[g * FF + j];
        arr[g] = (gtype == 2) ? tanhf(acc) : sigm(acc);
    }
    __syncthreads();
    if (tid < HH) {
        float gi = arr[tid], gc = arr[2*HH + tid], go = arr[3*HH + tid];
        last[HH + tid] = go * tanhf(gi * gc);      // f*c0 = 0
    }
    __syncthreads();

    // ---- fc0 + leaky: 64 threads, row-major float4 (L1/L2 cached) ----
    if (tid < HH) {
        const float4* w4 = (const float4*)(fc0_w + tid * 2 * HH);
        const float4* l4 = (const float4*)last;
        float b0 = 0.f, b1 = 0.f, b2 = 0.f, b3 = 0.f;
#pragma unroll
        for (int k = 0; k < 2 * HH / 4; k++) {
            float4 wv = w4[k], lv = l4[k];
            b0 += wv.x * lv.x; b1 += wv.y * lv.y;
            b2 += wv.z * lv.z; b3 += wv.w * lv.w;
        }
        out_sm[tid] = leaky(fc0_b[tid] + (b0 + b1) + (b2 + b3));
    }
    __syncthreads();

    // ---- fold the epilogue into scalars: tail, q, p0 ----
    int wid = tid >> 5, lane = tid & 31;
    if (wid < 3) {
        const float* w = (wid == 0) ? fc3_w : (wid == 1) ? (pred_w + HH) : pred_w;
        float v = out_sm[lane] * w[lane] + out_sm[lane + 32] * w[lane + 32];
#pragma unroll
        for (int o = 16; o; o >>= 1) v += __shfl_xor_sync(0xffffffffu, v, o);
        if (lane == 0) {
            if      (wid == 0) g_tail[s] = leaky(v + fc3_b[0]);
            else if (wid == 1) g_q[s]    = v;           // raw dot (no leaky)
            else               g_p0[s]   = v;           // raw dot (no leaky)
        }
    }
}

// ---------------------------------------------------------------------------
// prop: masked softmax over m + weighted sum of q  ->  prediction[b,n]
// head[b,n] is constant over m and cancels inside softmax (fc2 is dead).
// ---------------------------------------------------------------------------
__global__ __launch_bounds__(256) void prop_kernel(
    const float* __restrict__ rel_mask,
    const float* __restrict__ pred_b,
    float* __restrict__ out)
{
    __shared__ float tail_sm[NN];
    __shared__ float q_sm[NN];
    int b = blockIdx.y;
    int tid = threadIdx.x;
    for (int i = tid; i < NN; i += 256) {
        tail_sm[i] = g_tail[b * NN + i];
        q_sm[i]    = g_q[b * NN + i];
    }
    __syncthreads();

    int wid = tid >> 5, lane = tid & 31;
    int n = blockIdx.x * 8 + wid;
    const float* mrow = rel_mask + n * NN;
    const float* rrow = g_relw  + n * NN;

    float l[NN / 32];
    float mx = -1e30f;
#pragma unroll
    for (int j = 0; j < NN / 32; j++) {
        int m = j * 32 + lane;
        float v = mrow[m] + rrow[m] + tail_sm[m];
        l[j] = v;
        mx = fmaxf(mx, v);
    }
#pragma unroll
    for (int o = 16; o; o >>= 1) mx = fmaxf(mx, __shfl_xor_sync(0xffffffffu, mx, o));

    float se = 0.f, sq = 0.f;
#pragma unroll
    for (int j = 0; j < NN / 32; j++) {
        int m = j * 32 + lane;
        float e = __expf(l[j] - mx);
        se += e;
        sq += e * q_sm[m];
    }
#pragma unroll
    for (int o = 16; o; o >>= 1) {
        se += __shfl_xor_sync(0xffffffffu, se, o);
        sq += __shfl_xor_sync(0xffffffffu, sq, o);
    }
    if (lane == 0)
        out[b * NN + n] = leaky(g_p0[b * NN + n] + sq / se + pred_b[0]);
}

// ---------------------------------------------------------------------------
extern "C" void kernel_launch(void* const* d_in, const int* in_sizes, int n_in,
                              void* d_out, int out_size) {
    const float* x      = (const float*)d_in[0];
    const float* enc    = (const float*)d_in[1];
    const float* mask   = (const float*)d_in[2];
    const float* Wih_f  = (const float*)d_in[3];
    const float* Whh_f  = (const float*)d_in[4];
    const float* bih_f  = (const float*)d_in[5];
    const float* bhh_f  = (const float*)d_in[6];
    const float* Wih_b  = (const float*)d_in[7];
    // d_in[8] (Whh_b) unused: backward LSTM runs exactly one step from zero state
    const float* bih_b  = (const float*)d_in[9];
    const float* bhh_b  = (const float*)d_in[10];
    const float* fc0_w  = (const float*)d_in[11];
    const float* fc0_b  = (const float*)d_in[12];
    const float* fc1_w  = (const float*)d_in[13];
    const float* fc1_b  = (const float*)d_in[14];
    // d_in[15..16] (fc2) unused: head term is constant over softmax axis
    const float* fc3_w  = (const float*)d_in[17];
    const float* fc3_b  = (const float*)d_in[18];
    const float* pred_w = (const float*)d_in[19];
    const float* pred_b = (const float*)d_in[20];
    float* out = (float*)d_out;

    fused_kernel<<<NTOT, 256>>>(x, enc, Wih_f, Whh_f, bih_f, bhh_f,
                                Wih_b, bih_b, bhh_b,
                                fc0_w, fc0_b, fc1_w, fc1_b, fc3_w, fc3_b, pred_w);
    prop_kernel<<<dim3(NN / 8, BB), 256>>>(mask, pred_b, out);
}

// round 3
// speedup vs baseline: 1.3487x; 1.3487x over previous
#include <cuda_runtime.h>

// Problem constants
#define BB 4
#define TT 16
#define NN 512
#define FF 5
#define HH 64
#define SS 2048           // B*N sequences
#define RR 824
#define GG 256            // 4*H gates
#define R4 206            // RR/4 float4 per relation row
#define NSM 152           // GB300 SM count -> persistent 1 CTA/SM
#define NPAIR (NN*NN)     // 262144 relation pairs
#define RELW_WARPS (NSM*8)// 1216 streaming warps chip-wide

// Scratch (device globals; no allocation allowed)
__device__ float g_relw[NPAIR];   // leaky(enc . fc1_w + fc1_b)  [n,m]
__device__ float g_tail[SS];      // leaky(out . fc3_w + fc3_b)
__device__ float g_q[SS];         // out . pred_w[64:128]
__device__ float g_p0[SS];        // out . pred_w[0:64]

__device__ __forceinline__ float leaky(float v) { return v > 0.f ? v : 0.01f * v; }
// fast activations (err ~1e-6, fine at 1e-3 tolerance)
__device__ __forceinline__ float sigm(float v)   { return __fdividef(1.f, 1.f + __expf(-v)); }
__device__ __forceinline__ float tanhft(float v) { return 1.f - __fdividef(2.f, __expf(2.f * v) + 1.f); }

__device__ __forceinline__ void barn(int id, int cnt) {
    asm volatile("bar.sync %0, %1;" :: "r"(id), "r"(cnt) : "memory");
}

// ---------------------------------------------------------------------------
// Persistent fused kernel: 152 CTAs x 512 threads.
//   threads   0-255 (warps 0-7) : LSTM for this CTA's sequences, 4 at a time
//   threads 256-511 (warps 8-15): stream rel_encoding rows (DRAM-bound)
// The two halves never synchronize with each other (named barriers 1 and 2).
// ---------------------------------------------------------------------------
__global__ __launch_bounds__(512, 1) void fused_kernel(
    const float* __restrict__ x,
    const float* __restrict__ enc,
    const float* __restrict__ Wih_f, const float* __restrict__ Whh_f,
    const float* __restrict__ bih_f, const float* __restrict__ bhh_f,
    const float* __restrict__ Wih_b,
    const float* __restrict__ bih_b, const float* __restrict__ bhh_b,
    const float* __restrict__ fc0_w, const float* __restrict__ fc0_b,
    const float* __restrict__ fc1_w, const float* __restrict__ fc1_b,
    const float* __restrict__ fc3_w, const float* __restrict__ fc3_b,
    const float* __restrict__ pred_w)
{
    __shared__ float4 wsm[R4];                         // fc1 weights (relw half)
    __shared__ float xs[4 * TT * FF];                  // 4 seqs x 16 x 5
    __shared__ __align__(16) float hsm[4 * HH];        // hidden states
    __shared__ float arr[4 * GG];                      // activated gates
    __shared__ __align__(16) float last[4 * 2 * HH];   // [h_fwd_last, h_bwd_first]
    __shared__ float out_sm[4 * HH];

    int cta = blockIdx.x;
    int tid = threadIdx.x;

    if (tid >= 256) {
        // =================== relw half: DRAM streaming =====================
        int rt = tid - 256;
        const float4* w4g = (const float4*)fc1_w;
        for (int i = rt; i < R4; i += 256) wsm[i] = w4g[i];
        barn(2, 256);

        int wg = cta * 8 + (rt >> 5);                  // 0 .. 1215
        int lane = rt & 31;
        float fb = fc1_b[0];

        // Two pairs per iteration for deep MLP (14 LDG.128 in flight / warp).
        for (int p0 = wg; p0 < NPAIR; p0 += 2 * RELW_WARPS) {
            int p1 = p0 + RELW_WARPS;
            bool h2 = p1 < NPAIR;
            const float4* r0 = (const float4*)enc + (long long)p0 * R4;
            const float4* r1 = (const float4*)enc + (long long)p1 * R4;

            float4 a0 = __ldcs(r0 + lane);
            float4 a1 = __ldcs(r0 + lane + 32);
            float4 a2 = __ldcs(r0 + lane + 64);
            float4 a3 = __ldcs(r0 + lane + 96);
            float4 a4 = __ldcs(r0 + lane + 128);
            float4 a5 = __ldcs(r0 + lane + 160);
            float4 a6 = (lane < 14) ? __ldcs(r0 + lane + 192)
                                    : make_float4(0.f, 0.f, 0.f, 0.f);
            float4 b0, b1, b2, b3, b4, b5, b6;
            b0 = b1 = b2 = b3 = b4 = b5 = b6 = make_float4(0.f, 0.f, 0.f, 0.f);
            if (h2) {
                b0 = __ldcs(r1 + lane);
                b1 = __ldcs(r1 + lane + 32);
                b2 = __ldcs(r1 + lane + 64);
                b3 = __ldcs(r1 + lane + 96);
                b4 = __ldcs(r1 + lane + 128);
                b5 = __ldcs(r1 + lane + 160);
                if (lane < 14) b6 = __ldcs(r1 + lane + 192);
            }

            float s0 = 0.f, s1 = 0.f;
            float4 w;
            w = wsm[lane];
            s0 += a0.x*w.x + a0.y*w.y + a0.z*w.z + a0.w*w.w;
            s1 += b0.x*w.x + b0.y*w.y + b0.z*w.z + b0.w*w.w;
            w = wsm[lane + 32];
            s0 += a1.x*w.x + a1.y*w.y + a1.z*w.z + a1.w*w.w;
            s1 += b1.x*w.x + b1.y*w.y + b1.z*w.z + b1.w*w.w;
            w = wsm[lane + 64];
            s0 += a2.x*w.x + a2.y*w.y + a2.z*w.z + a2.w*w.w;
            s1 += b2.x*w.x + b2.y*w.y + b2.z*w.z + b2.w*w.w;
            w = wsm[lane + 96];
            s0 += a3.x*w.x + a3.y*w.y + a3.z*w.z + a3.w*w.w;
            s1 += b3.x*w.x + b3.y*w.y + b3.z*w.z + b3.w*w.w;
            w = wsm[lane + 128];
            s0 += a4.x*w.x + a4.y*w.y + a4.z*w.z + a4.w*w.w;
            s1 += b4.x*w.x + b4.y*w.y + b4.z*w.z + b4.w*w.w;
            w = wsm[lane + 160];
            s0 += a5.x*w.x + a5.y*w.y + a5.z*w.z + a5.w*w.w;
            s1 += b5.x*w.x + b5.y*w.y + b5.z*w.z + b5.w*w.w;
            if (lane < 14) {
                w = wsm[lane + 192];
                s0 += a6.x*w.x + a6.y*w.y + a6.z*w.z + a6.w*w.w;
                s1 += b6.x*w.x + b6.y*w.y + b6.z*w.z + b6.w*w.w;
            }
#pragma unroll
            for (int o = 16; o; o >>= 1) {
                s0 += __shfl_xor_sync(0xffffffffu, s0, o);
                s1 += __shfl_xor_sync(0xffffffffu, s1, o);
            }
            if (lane == 0) {
                g_relw[p0] = leaky(s0 + fb);
                if (h2) g_relw[p1] = leaky(s1 + fb);
            }
        }
        return;
    }

    // ======================= lstm half: warps 0-7 ==========================
    int g = tid;                       // gate index 0..255
    int gtype = g >> 6;                // 0=i 1=f 2=g 3=o (per-warp uniform)
    int us = tid >> 6, uj = tid & 63;  // update-phase role: (seq, unit)
    int wid = tid >> 5, lane = tid & 31;

    // Sequence range for this CTA: 2048 = 152*13 + 72
    int base = 13 * cta + (cta < 72 ? cta : 72);
    int cnt  = 13 + (cta < 72 ? 1 : 0);

    // Hoisted per-gate weights
    float wh[HH];
#pragma unroll
    for (int j = 0; j < HH / 4; j++) {
        float4 v = ((const float4*)Whh_f)[g * (HH / 4) + j];
        wh[4*j] = v.x; wh[4*j+1] = v.y; wh[4*j+2] = v.z; wh[4*j+3] = v.w;
    }
    float wf0 = Wih_f[g*FF],   wf1 = Wih_f[g*FF+1], wf2 = Wih_f[g*FF+2],
          wf3 = Wih_f[g*FF+3], wf4 = Wih_f[g*FF+4];
    float bsum = bih_f[g] + bhh_f[g];
    float wb0 = Wih_b[g*FF],   wb1 = Wih_b[g*FF+1], wb2 = Wih_b[g*FF+2],
          wb3 = Wih_b[g*FF+3], wb4 = Wih_b[g*FF+4];
    float bb = bih_b[g] + bhh_b[g];

    for (int g0 = 0; g0 < cnt; g0 += 4) {
        int ns = cnt - g0; if (ns > 4) ns = 4;

        // Load 4x16x5 input slices (zero-fill inactive sequences)
        for (int i = tid; i < 4 * TT * FF; i += 256) {
            float v = 0.f;
            if (i < ns * TT * FF) {
                int s = i / (TT * FF), r = i - s * (TT * FF);
                int t = r / FF, f = r - t * FF;
                int sg = base + g0 + s;
                int b = sg >> 9, n = sg & (NN - 1);
                v = x[((b * TT + t) * NN + n) * FF + f];
            }
            xs[i] = v;
        }
        hsm[tid] = 0.f;
        float creg = 0.f;
        barn(1, 256);

        // ---- forward recurrence: 16 steps x 4 sequences ----
#pragma unroll 1
        for (int t = 0; t < TT; t++) {
            float av[4];
#pragma unroll
            for (int s = 0; s < 4; s++) {
                const float* xt = xs + s * (TT * FF) + t * FF;
                float acc = bsum + xt[0]*wf0 + xt[1]*wf1 + xt[2]*wf2
                                 + xt[3]*wf3 + xt[4]*wf4;
                const float4* h4 = (const float4*)(hsm + s * HH);
                float p0 = 0.f, p1 = 0.f, p2 = 0.f, p3 = 0.f;
#pragma unroll
                for (int k = 0; k < HH / 4; k++) {
                    float4 hv = h4[k];
                    p0 += hv.x * wh[4*k];
                    p1 += hv.y * wh[4*k+1];
                    p2 += hv.z * wh[4*k+2];
                    p3 += hv.w * wh[4*k+3];
                }
                av[s] = acc + (p0 + p1) + (p2 + p3);
            }
#pragma unroll
            for (int s = 0; s < 4; s++)
                arr[s * GG + g] = (gtype == 2) ? tanhft(av[s]) : sigm(av[s]);
            barn(1, 256);
            {
                float gi = arr[us*GG + uj],        gf = arr[us*GG + HH + uj];
                float gc = arr[us*GG + 2*HH + uj], go = arr[us*GG + 3*HH + uj];
                creg = gf * creg + gi * gc;
                hsm[us * HH + uj] = go * tanhft(creg);
            }
            barn(1, 256);
        }
        last[us * 2 * HH + uj] = hsm[tid];

        // ---- backward LSTM: one step from zero state on x[T-1] ----
#pragma unroll
        for (int s = 0; s < 4; s++) {
            const float* xt = xs + s * (TT * FF) + (TT - 1) * FF;
            float acc = bb + xt[0]*wb0 + xt[1]*wb1 + xt[2]*wb2
                           + xt[3]*wb3 + xt[4]*wb4;
            arr[s * GG + g] = (gtype == 2) ? tanhft(acc) : sigm(acc);
        }
        barn(1, 256);
        {
            float gi = arr[us*GG + uj], gc = arr[us*GG + 2*HH + uj];
            float go = arr[us*GG + 3*HH + uj];
            last[us * 2 * HH + HH + uj] = go * tanhft(gi * gc);   // f*c0 = 0
        }
        barn(1, 256);

        // ---- fc0 + leaky ----
        {
            const float4* w4 = (const float4*)(fc0_w + uj * 2 * HH);
            const float4* l4 = (const float4*)(last + us * 2 * HH);
            float c0 = 0.f, c1 = 0.f, c2 = 0.f, c3 = 0.f;
#pragma unroll
            for (int k = 0; k < 2 * HH / 4; k++) {
                float4 wv = w4[k], lv = l4[k];
                c0 += wv.x * lv.x; c1 += wv.y * lv.y;
                c2 += wv.z * lv.z; c3 += wv.w * lv.w;
            }
            out_sm[us * HH + uj] = leaky(fc0_b[uj] + (c0 + c1) + (c2 + c3));
        }
        barn(1, 256);

        // ---- epilogue scalars: warps 0,2,4,6 handle seq wid/2 ----
        if ((wid & 1) == 0) {
            int s = wid >> 1;
            if (s < ns) {
                int sg = base + g0 + s;
                const float* o = out_sm + s * HH;
#pragma unroll
                for (int which = 0; which < 3; which++) {
                    const float* w = (which == 0) ? fc3_w
                                   : (which == 1) ? (pred_w + HH) : pred_w;
                    float v = o[lane] * w[lane] + o[lane + 32] * w[lane + 32];
#pragma unroll
                    for (int off = 16; off; off >>= 1)
                        v += __shfl_xor_sync(0xffffffffu, v, off);
                    if (lane == 0) {
                        if      (which == 0) g_tail[sg] = leaky(v + fc3_b[0]);
                        else if (which == 1) g_q[sg]    = v;
                        else                 g_p0[sg]   = v;
                    }
                }
            }
        }
        barn(1, 256);   // protect xs/arr before next group overwrites
    }
}

// ---------------------------------------------------------------------------
// prop: masked softmax over m + weighted sum of q  ->  prediction[b,n]
// head[b,n] is constant over m and cancels inside softmax (fc2 is dead).
// ---------------------------------------------------------------------------
__global__ __launch_bounds__(256) void prop_kernel(
    const float* __restrict__ rel_mask,
    const float* __restrict__ pred_b,
    float* __restrict__ out)
{
    __shared__ float tail_sm[NN];
    __shared__ float q_sm[NN];
    int b = blockIdx.y;
    int tid = threadIdx.x;
    for (int i = tid; i < NN; i += 256) {
        tail_sm[i] = g_tail[b * NN + i];
        q_sm[i]    = g_q[b * NN + i];
    }
    __syncthreads();

    int wid = tid >> 5, lane = tid & 31;
    int n = blockIdx.x * 8 + wid;
    const float* mrow = rel_mask + n * NN;
    const float* rrow = g_relw  + n * NN;

    float l[NN / 32];
    float mx = -1e30f;
#pragma unroll
    for (int j = 0; j < NN / 32; j++) {
        int m = j * 32 + lane;
        float v = mrow[m] + rrow[m] + tail_sm[m];
        l[j] = v;
        mx = fmaxf(mx, v);
    }
#pragma unroll
    for (int o = 16; o; o >>= 1) mx = fmaxf(mx, __shfl_xor_sync(0xffffffffu, mx, o));

    float se = 0.f, sq = 0.f;
#pragma unroll
    for (int j = 0; j < NN / 32; j++) {
        int m = j * 32 + lane;
        float e = __expf(l[j] - mx);
        se += e;
        sq += e * q_sm[m];
    }
#pragma unroll
    for (int o = 16; o; o >>= 1) {
        se += __shfl_xor_sync(0xffffffffu, se, o);
        sq += __shfl_xor_sync(0xffffffffu, sq, o);
    }
    if (lane == 0)
        out[b * NN + n] = leaky(g_p0[b * NN + n] + sq / se + pred_b[0]);
}

// ---------------------------------------------------------------------------
extern "C" void kernel_launch(void* const* d_in, const int* in_sizes, int n_in,
                              void* d_out, int out_size) {
    const float* x      = (const float*)d_in[0];
    const float* enc    = (const float*)d_in[1];
    const float* mask   = (const float*)d_in[2];
    const float* Wih_f  = (const float*)d_in[3];
    const float* Whh_f  = (const float*)d_in[4];
    const float* bih_f  = (const float*)d_in[5];
    const float* bhh_f  = (const float*)d_in[6];
    const float* Wih_b  = (const float*)d_in[7];
    // d_in[8] (Whh_b) unused: backward LSTM runs exactly one step from zero state
    const float* bih_b  = (const float*)d_in[9];
    const float* bhh_b  = (const float*)d_in[10];
    const float* fc0_w  = (const float*)d_in[11];
    const float* fc0_b  = (const float*)d_in[12];
    const float* fc1_w  = (const float*)d_in[13];
    const float* fc1_b  = (const float*)d_in[14];
    // d_in[15..16] (fc2) unused: head term is constant over softmax axis
    const float* fc3_w  = (const float*)d_in[17];
    const float* fc3_b  = (const float*)d_in[18];
    const float* pred_w = (const float*)d_in[19];
    const float* pred_b = (const float*)d_in[20];
    float* out = (float*)d_out;

    fused_kernel<<<NSM, 512>>>(x, enc, Wih_f, Whh_f, bih_f, bhh_f,
                               Wih_b, bih_b, bhh_b,
                               fc0_w, fc0_b, fc1_w, fc1_b, fc3_w, fc3_b, pred_w);
    prop_kernel<<<dim3(NN / 8, BB), 256>>>(mask, pred_b, out);
}

// round 4
// speedup vs baseline: 2.3706x; 1.7577x over previous
#include <cuda_runtime.h>

// Problem constants
#define BB 4
#define TT 16
#define NN 512
#define FF 5
#define HH 64
#define SS 2048           // B*N sequences
#define RR 824
#define GG 256            // 4*H gates
#define R4 206            // RR/4 float4 per relation row
#define NSM 152           // GB300 SM count -> persistent 1 CTA/SM
#define NPAIR (NN*NN)     // 262144 relation pairs
#define NWARPS (NSM*16)   // 2432 warps chip-wide in the fused kernel

// Scratch (device globals; no allocation allowed).
// g_relw: only entries with rel_mask==0 are ever written; masked entries stay
// 0.0 (static zero-init) and are annihilated by the -1e9 mask in the softmax,
// exactly as in the reference (exp underflows to 0 in fp32). Deterministic.
__device__ float g_relw[NPAIR];
__device__ float g_tail[SS];      // leaky(out . fc3_w + fc3_b)
__device__ float g_q[SS];         // out . pred_w[64:128]
__device__ float g_p0[SS];        // out . pred_w[0:64]

__device__ __forceinline__ float leaky(float v) { return v > 0.f ? v : 0.01f * v; }
// fast activations (err ~1e-6, fine at 1e-3 tolerance)
__device__ __forceinline__ float sigm(float v)   { return __fdividef(1.f, 1.f + __expf(-v)); }
__device__ __forceinline__ float tanhft(float v) { return 1.f - __fdividef(2.f, __expf(2.f * v) + 1.f); }

// ---------------------------------------------------------------------------
// Persistent fused kernel: 152 CTAs x 512 threads.
// Phase 1 (all threads): sparse rel_weight — stream ONLY rows with mask==0.
// Phase 2 (all threads): LSTM, 8 sequences per group (thread = (seq-half, gate)).
// ---------------------------------------------------------------------------
__global__ __launch_bounds__(512, 1) void fused_kernel(
    const float* __restrict__ x,
    const float* __restrict__ enc,
    const float* __restrict__ rel_mask,
    const float* __restrict__ Wih_f, const float* __restrict__ Whh_f,
    const float* __restrict__ bih_f, const float* __restrict__ bhh_f,
    const float* __restrict__ Wih_b,
    const float* __restrict__ bih_b, const float* __restrict__ bhh_b,
    const float* __restrict__ fc0_w, const float* __restrict__ fc0_b,
    const float* __restrict__ fc1_w, const float* __restrict__ fc1_b,
    const float* __restrict__ fc3_w, const float* __restrict__ fc3_b,
    const float* __restrict__ pred_w)
{
    __shared__ float4 wsm[R4];                         // fc1 weights
    __shared__ float xs[8 * TT * FF];                  // 8 seqs x 16 x 5
    __shared__ __align__(16) float hsm[8 * HH];        // hidden states
    __shared__ float arr[8 * GG];                      // activated gates
    __shared__ __align__(16) float last[8 * 2 * HH];   // [h_fwd, h_bwd_first]
    __shared__ float out_sm[8 * HH];

    int cta = blockIdx.x;
    int tid = threadIdx.x;
    int wid = tid >> 5, lane = tid & 31;

    // ======================= Phase 1: sparse relw ==========================
    const float4* w4g = (const float4*)fc1_w;
    for (int i = tid; i < R4; i += 512) wsm[i] = w4g[i];
    __syncthreads();

    {
        int gw = cta * 16 + wid;                       // 0 .. 2431
        float fb = fc1_b[0];
        for (int p = gw; p < NPAIR; p += NWARPS) {
            float mv = __ldg(rel_mask + p);            // broadcast
            if (mv != 0.f) continue;                   // masked: exp -> 0, skip
            const float4* row = (const float4*)enc + (long long)p * R4;
            float4 a0 = __ldcs(row + lane);
            float4 a1 = __ldcs(row + lane + 32);
            float4 a2 = __ldcs(row + lane + 64);
            float4 a3 = __ldcs(row + lane + 96);
            float4 a4 = __ldcs(row + lane + 128);
            float4 a5 = __ldcs(row + lane + 160);
            float4 a6 = (lane < 14) ? __ldcs(row + lane + 192)
                                    : make_float4(0.f, 0.f, 0.f, 0.f);
            float s0 = 0.f;
            float4 w;
            w = wsm[lane];       s0 += a0.x*w.x + a0.y*w.y + a0.z*w.z + a0.w*w.w;
            w = wsm[lane + 32];  s0 += a1.x*w.x + a1.y*w.y + a1.z*w.z + a1.w*w.w;
            w = wsm[lane + 64];  s0 += a2.x*w.x + a2.y*w.y + a2.z*w.z + a2.w*w.w;
            w = wsm[lane + 96];  s0 += a3.x*w.x + a3.y*w.y + a3.z*w.z + a3.w*w.w;
            w = wsm[lane + 128]; s0 += a4.x*w.x + a4.y*w.y + a4.z*w.z + a4.w*w.w;
            w = wsm[lane + 160]; s0 += a5.x*w.x + a5.y*w.y + a5.z*w.z + a5.w*w.w;
            if (lane < 14) {
                w = wsm[lane + 192];
                s0 += a6.x*w.x + a6.y*w.y + a6.z*w.z + a6.w*w.w;
            }
#pragma unroll
            for (int o = 16; o; o >>= 1) s0 += __shfl_xor_sync(0xffffffffu, s0, o);
            if (lane == 0) g_relw[p] = leaky(s0 + fb);
        }
    }
    __syncthreads();

    // ======================= Phase 2: LSTM =================================
    int half = tid >> 8;               // which 4-seq sub-block this thread computes
    int g = tid & 255;                 // gate index 0..255
    int gtype = g >> 6;                // 0=i 1=f 2=g 3=o (per-warp uniform)
    int us = tid >> 6, uj = tid & 63;  // update/fc0 role: (seq 0..7, unit 0..63)

    // Sequence range: 2048 = 152*13 + 72
    int base = 13 * cta + (cta < 72 ? cta : 72);
    int cnt  = 13 + (cta < 72 ? 1 : 0);

    // Hoisted per-gate weights
    float wh[HH];
#pragma unroll
    for (int j = 0; j < HH / 4; j++) {
        float4 v = ((const float4*)Whh_f)[g * (HH / 4) + j];
        wh[4*j] = v.x; wh[4*j+1] = v.y; wh[4*j+2] = v.z; wh[4*j+3] = v.w;
    }
    float wf0 = Wih_f[g*FF],   wf1 = Wih_f[g*FF+1], wf2 = Wih_f[g*FF+2],
          wf3 = Wih_f[g*FF+3], wf4 = Wih_f[g*FF+4];
    float bsum = bih_f[g] + bhh_f[g];

    for (int g0 = 0; g0 < cnt; g0 += 8) {
        int ns = cnt - g0; if (ns > 8) ns = 8;

        // Load 8x16x5 input slices (zero-fill inactive sequences)
        for (int i = tid; i < 8 * TT * FF; i += 512) {
            float v = 0.f;
            if (i < ns * TT * FF) {
                int s = i / (TT * FF), r = i - s * (TT * FF);
                int t = r / FF, f = r - t * FF;
                int sg = base + g0 + s;
                int b = sg >> 9, n = sg & (NN - 1);
                v = x[((b * TT + t) * NN + n) * FF + f];
            }
            xs[i] = v;
        }
        hsm[tid] = 0.f;                 // 8*64 = 512 == blockDim
        float creg = 0.f;
        __syncthreads();

        // ---- forward recurrence: 16 steps x 8 sequences ----
#pragma unroll 1
        for (int t = 0; t < TT; t++) {
            float av[4];
#pragma unroll
            for (int s4 = 0; s4 < 4; s4++) {
                int s = half * 4 + s4;
                const float* xt = xs + s * (TT * FF) + t * FF;
                float acc = bsum + xt[0]*wf0 + xt[1]*wf1 + xt[2]*wf2
                                 + xt[3]*wf3 + xt[4]*wf4;
                const float4* h4 = (const float4*)(hsm + s * HH);
                float p0 = 0.f, p1 = 0.f, p2 = 0.f, p3 = 0.f;
#pragma unroll
                for (int k = 0; k < HH / 4; k++) {
                    float4 hv = h4[k];
                    p0 += hv.x * wh[4*k];
                    p1 += hv.y * wh[4*k+1];
                    p2 += hv.z * wh[4*k+2];
                    p3 += hv.w * wh[4*k+3];
                }
                av[s4] = acc + (p0 + p1) + (p2 + p3);
            }
#pragma unroll
            for (int s4 = 0; s4 < 4; s4++)
                arr[(half * 4 + s4) * GG + g] =
                    (gtype == 2) ? tanhft(av[s4]) : sigm(av[s4]);
            __syncthreads();
            {
                float gi = arr[us*GG + uj],        gf = arr[us*GG + HH + uj];
                float gc = arr[us*GG + 2*HH + uj], go = arr[us*GG + 3*HH + uj];
                creg = gf * creg + gi * gc;
                hsm[us * HH + uj] = go * tanhft(creg);
            }
            __syncthreads();
        }
        last[us * 2 * HH + uj] = hsm[tid];

        // ---- backward LSTM: one step from zero state on x[T-1] ----
        {
            float wb0 = Wih_b[g*FF],   wb1 = Wih_b[g*FF+1], wb2 = Wih_b[g*FF+2],
                  wb3 = Wih_b[g*FF+3], wb4 = Wih_b[g*FF+4];
            float bb = bih_b[g] + bhh_b[g];
#pragma unroll
            for (int s4 = 0; s4 < 4; s4++) {
                int s = half * 4 + s4;
                const float* xt = xs + s * (TT * FF) + (TT - 1) * FF;
                float acc = bb + xt[0]*wb0 + xt[1]*wb1 + xt[2]*wb2
                               + xt[3]*wb3 + xt[4]*wb4;
                arr[s * GG + g] = (gtype == 2) ? tanhft(acc) : sigm(acc);
            }
        }
        __syncthreads();
        {
            float gi = arr[us*GG + uj], gc = arr[us*GG + 2*HH + uj];
            float go = arr[us*GG + 3*HH + uj];
            last[us * 2 * HH + HH + uj] = go * tanhft(gi * gc);   // f*c0 = 0
        }
        __syncthreads();

        // ---- fc0 + leaky ----
        {
            const float4* w4 = (const float4*)(fc0_w + uj * 2 * HH);
            const float4* l4 = (const float4*)(last + us * 2 * HH);
            float c0 = 0.f, c1 = 0.f, c2 = 0.f, c3 = 0.f;
#pragma unroll
            for (int k = 0; k < 2 * HH / 4; k++) {
                float4 wv = w4[k], lv = l4[k];
                c0 += wv.x * lv.x; c1 += wv.y * lv.y;
                c2 += wv.z * lv.z; c3 += wv.w * lv.w;
            }
            out_sm[us * HH + uj] = leaky(fc0_b[uj] + (c0 + c1) + (c2 + c3));
        }
        __syncthreads();

        // ---- epilogue scalars: 2 warps per sequence ----
        {
            int s = wid >> 1;
            if (s < ns) {
                int sg = base + g0 + s;
                const float* o = out_sm + s * HH;
                if ((wid & 1) == 0) {
                    // which 0 (tail) and 1 (q)
#pragma unroll
                    for (int which = 0; which < 2; which++) {
                        const float* w = (which == 0) ? fc3_w : (pred_w + HH);
                        float v = o[lane] * w[lane] + o[lane + 32] * w[lane + 32];
#pragma unroll
                        for (int off = 16; off; off >>= 1)
                            v += __shfl_xor_sync(0xffffffffu, v, off);
                        if (lane == 0) {
                            if (which == 0) g_tail[sg] = leaky(v + fc3_b[0]);
                            else            g_q[sg]    = v;
                        }
                    }
                } else {
                    // which 2 (p0)
                    float v = o[lane] * pred_w[lane] + o[lane + 32] * pred_w[lane + 32];
#pragma unroll
                    for (int off = 16; off; off >>= 1)
                        v += __shfl_xor_sync(0xffffffffu, v, off);
                    if (lane == 0) g_p0[sg] = v;
                }
            }
        }
        __syncthreads();   // protect xs/arr before next group overwrites
    }
}

// ---------------------------------------------------------------------------
// prop: masked softmax over m + weighted sum of q  ->  prediction[b,n]
// head[b,n] is constant over m and cancels inside softmax (fc2 is dead).
// float4 loads: 4 LDG.128 per lane per row (good MLP).
// ---------------------------------------------------------------------------
__global__ __launch_bounds__(256) void prop_kernel(
    const float* __restrict__ rel_mask,
    const float* __restrict__ pred_b,
    float* __restrict__ out)
{
    __shared__ __align__(16) float tail_sm[NN];
    __shared__ __align__(16) float q_sm[NN];
    int b = blockIdx.y;
    int tid = threadIdx.x;
    for (int i = tid; i < NN; i += 256) {
        tail_sm[i] = g_tail[b * NN + i];
        q_sm[i]    = g_q[b * NN + i];
    }
    __syncthreads();

    int wid = tid >> 5, lane = tid & 31;
    int n = blockIdx.x * 8 + wid;
    const float4* m4 = (const float4*)(rel_mask + n * NN);
    const float4* r4 = (const float4*)(g_relw  + n * NN);
    const float4* t4 = (const float4*)tail_sm;

    float4 l[4];
    float mx = -1e30f;
#pragma unroll
    for (int j = 0; j < 4; j++) {
        int idx = j * 32 + lane;
        float4 mv = m4[idx], rv = r4[idx], tv = t4[idx];
        l[j].x = mv.x + rv.x + tv.x;
        l[j].y = mv.y + rv.y + tv.y;
        l[j].z = mv.z + rv.z + tv.z;
        l[j].w = mv.w + rv.w + tv.w;
        mx = fmaxf(mx, fmaxf(fmaxf(l[j].x, l[j].y), fmaxf(l[j].z, l[j].w)));
    }
#pragma unroll
    for (int o = 16; o; o >>= 1) mx = fmaxf(mx, __shfl_xor_sync(0xffffffffu, mx, o));

    const float4* q4 = (const float4*)q_sm;
    float se = 0.f, sq = 0.f;
#pragma unroll
    for (int j = 0; j < 4; j++) {
        int idx = j * 32 + lane;
        float4 qv = q4[idx];
        float e0 = __expf(l[j].x - mx);
        float e1 = __expf(l[j].y - mx);
        float e2 = __expf(l[j].z - mx);
        float e3 = __expf(l[j].w - mx);
        se += (e0 + e1) + (e2 + e3);
        sq += (e0 * qv.x + e1 * qv.y) + (e2 * qv.z + e3 * qv.w);
    }
#pragma unroll
    for (int o = 16; o; o >>= 1) {
        se += __shfl_xor_sync(0xffffffffu, se, o);
        sq += __shfl_xor_sync(0xffffffffu, sq, o);
    }
    if (lane == 0)
        out[b * NN + n] = leaky(g_p0[b * NN + n] + sq / se + pred_b[0]);
}

// ---------------------------------------------------------------------------
extern "C" void kernel_launch(void* const* d_in, const int* in_sizes, int n_in,
                              void* d_out, int out_size) {
    const float* x      = (const float*)d_in[0];
    const float* enc    = (const float*)d_in[1];
    const float* mask   = (const float*)d_in[2];
    const float* Wih_f  = (const float*)d_in[3];
    const float* Whh_f  = (const float*)d_in[4];
    const float* bih_f  = (const float*)d_in[5];
    const float* bhh_f  = (const float*)d_in[6];
    const float* Wih_b  = (const float*)d_in[7];
    // d_in[8] (Whh_b) unused: backward LSTM runs exactly one step from zero state
    const float* bih_b  = (const float*)d_in[9];
    const float* bhh_b  = (const float*)d_in[10];
    const float* fc0_w  = (const float*)d_in[11];
    const float* fc0_b  = (const float*)d_in[12];
    const float* fc1_w  = (const float*)d_in[13];
    const float* fc1_b  = (const float*)d_in[14];
    // d_in[15..16] (fc2) unused: head term is constant over softmax axis
    const float* fc3_w  = (const float*)d_in[17];
    const float* fc3_b  = (const float*)d_in[18];
    const float* pred_w = (const float*)d_in[19];
    const float* pred_b = (const float*)d_in[20];
    float* out = (float*)d_out;

    fused_kernel<<<NSM, 512>>>(x, enc, mask, Wih_f, Whh_f, bih_f, bhh_f,
                               Wih_b, bih_b, bhh_b,
                               fc0_w, fc0_b, fc1_w, fc1_b, fc3_w, fc3_b, pred_w);
    prop_kernel<<<dim3(NN / 8, BB), 256>>>(mask, pred_b, out);
}

// round 5
// speedup vs baseline: 2.4921x; 1.0513x over previous
#include <cuda_runtime.h>

// Problem constants
#define BB 4
#define TT 16
#define NN 512
#define FF 5
#define HH 64
#define SS 2048           // B*N sequences
#define RR 824
#define GG 256            // 4*H gates
#define R4 206            // RR/4 float4 per relation row
#define NSM 152           // GB300 SM count -> persistent 1 CTA/SM
#define NPAIR (NN*NN)     // 262144 relation pairs
#define NCHUNK (NPAIR/32) // 8192 32-pair chunks
#define NWARPS (NSM*16)   // 2432 warps chip-wide

// Scratch (device globals; no allocation allowed).
// g_relw: only entries with rel_mask==0 are ever written; masked entries stay
// 0.0 (static zero-init) and are annihilated by the -1e9 mask in the softmax,
// exactly as in the reference (exp underflows to 0 in fp32). Deterministic.
__device__ float g_relw[NPAIR];
__device__ float g_tail[SS];      // leaky(out . fc3_w + fc3_b)
__device__ float g_q[SS];         // out . pred_w[64:128]
__device__ float g_p0[SS];        // out . pred_w[0:64]

// Grid-wide barrier state (generation-based: safe across graph replays).
__device__ unsigned int g_bar_count = 0;
__device__ unsigned int g_bar_gen   = 0;

__device__ __forceinline__ float leaky(float v) { return v > 0.f ? v : 0.01f * v; }
// fast activations (err ~1e-6, fine at 1e-3 tolerance)
__device__ __forceinline__ float sigm(float v)   { return __fdividef(1.f, 1.f + __expf(-v)); }
__device__ __forceinline__ float tanhft(float v) { return 1.f - __fdividef(2.f, __expf(2.f * v) + 1.f); }

// One 824-length dot product, 32 lanes cooperating; returns lane-0 sum.
__device__ __forceinline__ float row_dot(const float4* __restrict__ row,
                                         const float4* __restrict__ wsm,
                                         int lane) {
    float4 a0 = __ldcs(row + lane);
    float4 a1 = __ldcs(row + lane + 32);
    float4 a2 = __ldcs(row + lane + 64);
    float4 a3 = __ldcs(row + lane + 96);
    float4 a4 = __ldcs(row + lane + 128);
    float4 a5 = __ldcs(row + lane + 160);
    float4 a6 = (lane < 14) ? __ldcs(row + lane + 192)
                            : make_float4(0.f, 0.f, 0.f, 0.f);
    float s = 0.f;
    float4 w;
    w = wsm[lane];       s += a0.x*w.x + a0.y*w.y + a0.z*w.z + a0.w*w.w;
    w = wsm[lane + 32];  s += a1.x*w.x + a1.y*w.y + a1.z*w.z + a1.w*w.w;
    w = wsm[lane + 64];  s += a2.x*w.x + a2.y*w.y + a2.z*w.z + a2.w*w.w;
    w = wsm[lane + 96];  s += a3.x*w.x + a3.y*w.y + a3.z*w.z + a3.w*w.w;
    w = wsm[lane + 128]; s += a4.x*w.x + a4.y*w.y + a4.z*w.z + a4.w*w.w;
    w = wsm[lane + 160]; s += a5.x*w.x + a5.y*w.y + a5.z*w.z + a5.w*w.w;
    if (lane < 14) {
        w = wsm[lane + 192];
        s += a6.x*w.x + a6.y*w.y + a6.z*w.z + a6.w*w.w;
    }
#pragma unroll
    for (int o = 16; o; o >>= 1) s += __shfl_xor_sync(0xffffffffu, s, o);
    return s;
}

// ---------------------------------------------------------------------------
// Single persistent kernel: 152 CTAs x 512 threads (one per SM, one wave).
// Phase 1: sparse rel_weight via ballot mask-scan (coalesced mask loads).
// Phase 2: LSTM, 8 sequences per group.
// Grid barrier, then Phase 3: masked softmax + prediction (one warp per row).
// ---------------------------------------------------------------------------
__global__ __launch_bounds__(512, 1) void fused_kernel(
    const float* __restrict__ x,
    const float* __restrict__ enc,
    const float* __restrict__ rel_mask,
    const float* __restrict__ Wih_f, const float* __restrict__ Whh_f,
    const float* __restrict__ bih_f, const float* __restrict__ bhh_f,
    const float* __restrict__ Wih_b,
    const float* __restrict__ bih_b, const float* __restrict__ bhh_b,
    const float* __restrict__ fc0_w, const float* __restrict__ fc0_b,
    const float* __restrict__ fc1_w, const float* __restrict__ fc1_b,
    const float* __restrict__ fc3_w, const float* __restrict__ fc3_b,
    const float* __restrict__ pred_w, const float* __restrict__ pred_b,
    float* __restrict__ out)
{
    __shared__ float4 wsm[R4];                         // fc1 weights
    __shared__ float xs[8 * TT * FF];                  // 8 seqs x 16 x 5
    __shared__ __align__(16) float hsm[8 * HH];        // hidden states
    __shared__ float arr[8 * GG];                      // activated gates
    __shared__ __align__(16) float last[8 * 2 * HH];   // [h_fwd, h_bwd_first]
    __shared__ float out_sm[8 * HH];

    int cta = blockIdx.x;
    int tid = threadIdx.x;
    int wid = tid >> 5, lane = tid & 31;

    // Snapshot barrier generation BEFORE any arrival can happen this launch.
    unsigned int my_gen = *((volatile unsigned int*)&g_bar_gen);

    // ============ Phase 1: sparse relw with ballot mask scan ===============
    const float4* w4g = (const float4*)fc1_w;
    for (int i = tid; i < R4; i += 512) wsm[i] = w4g[i];
    __syncthreads();

    {
        float fb = fc1_b[0];
        for (int c = cta * 16 + wid; c < NCHUNK; c += NWARPS) {
            int pb = c * 32;
            float mv = rel_mask[pb + lane];            // coalesced 128B load
            unsigned act = __ballot_sync(0xffffffffu, mv == 0.f);
            while (act) {
                int b0 = __ffs(act) - 1; act &= act - 1;
                int b1 = -1;
                if (act) { b1 = __ffs(act) - 1; act &= act - 1; }
                const float4* r0 = (const float4*)enc + (long long)(pb + b0) * R4;
                float s0 = row_dot(r0, wsm, lane);
                float s1 = 0.f;
                if (b1 >= 0) {
                    const float4* r1 = (const float4*)enc + (long long)(pb + b1) * R4;
                    s1 = row_dot(r1, wsm, lane);
                }
                if (lane == 0) {
                    g_relw[pb + b0] = leaky(s0 + fb);
                    if (b1 >= 0) g_relw[pb + b1] = leaky(s1 + fb);
                }
            }
        }
    }
    __syncthreads();

    // ======================= Phase 2: LSTM =================================
    int half = tid >> 8;               // which 4-seq sub-block
    int g = tid & 255;                 // gate index 0..255
    int gtype = g >> 6;                // 0=i 1=f 2=g 3=o (per-warp uniform)
    int us = tid >> 6, uj = tid & 63;  // update/fc0 role: (seq 0..7, unit 0..63)

    // Sequence range: 2048 = 152*13 + 72
    int base = 13 * cta + (cta < 72 ? cta : 72);
    int cnt  = 13 + (cta < 72 ? 1 : 0);

    // Hoisted per-gate weights
    float wh[HH];
#pragma unroll
    for (int j = 0; j < HH / 4; j++) {
        float4 v = ((const float4*)Whh_f)[g * (HH / 4) + j];
        wh[4*j] = v.x; wh[4*j+1] = v.y; wh[4*j+2] = v.z; wh[4*j+3] = v.w;
    }
    float wf0 = Wih_f[g*FF],   wf1 = Wih_f[g*FF+1], wf2 = Wih_f[g*FF+2],
          wf3 = Wih_f[g*FF+3], wf4 = Wih_f[g*FF+4];
    float bsum = bih_f[g] + bhh_f[g];

    for (int g0 = 0; g0 < cnt; g0 += 8) {
        int ns = cnt - g0; if (ns > 8) ns = 8;

        // Load 8x16x5 input slices (zero-fill inactive sequences)
        for (int i = tid; i < 8 * TT * FF; i += 512) {
            float v = 0.f;
            if (i < ns * TT * FF) {
                int s = i / (TT * FF), r = i - s * (TT * FF);
                int t = r / FF, f = r - t * FF;
                int sg = base + g0 + s;
                int b = sg >> 9, n = sg & (NN - 1);
                v = x[((b * TT + t) * NN + n) * FF + f];
            }
            xs[i] = v;
        }
        hsm[tid] = 0.f;                 // 8*64 = 512 == blockDim
        float creg = 0.f;
        __syncthreads();

        // ---- forward recurrence: 16 steps x 8 sequences ----
#pragma unroll 1
        for (int t = 0; t < TT; t++) {
            float av[4];
#pragma unroll
            for (int s4 = 0; s4 < 4; s4++) {
                int s = half * 4 + s4;
                const float* xt = xs + s * (TT * FF) + t * FF;
                float acc = bsum + xt[0]*wf0 + xt[1]*wf1 + xt[2]*wf2
                                 + xt[3]*wf3 + xt[4]*wf4;
                const float4* h4 = (const float4*)(hsm + s * HH);
                float p0 = 0.f, p1 = 0.f, p2 = 0.f, p3 = 0.f;
#pragma unroll
                for (int k = 0; k < HH / 4; k++) {
                    float4 hv = h4[k];
                    p0 += hv.x * wh[4*k];
                    p1 += hv.y * wh[4*k+1];
                    p2 += hv.z * wh[4*k+2];
                    p3 += hv.w * wh[4*k+3];
                }
                av[s4] = acc + (p0 + p1) + (p2 + p3);
            }
#pragma unroll
            for (int s4 = 0; s4 < 4; s4++)
                arr[(half * 4 + s4) * GG + g] =
                    (gtype == 2) ? tanhft(av[s4]) : sigm(av[s4]);
            __syncthreads();
            {
                float gi = arr[us*GG + uj],        gf = arr[us*GG + HH + uj];
                float gc = arr[us*GG + 2*HH + uj], go = arr[us*GG + 3*HH + uj];
                creg = gf * creg + gi * gc;
                hsm[us * HH + uj] = go * tanhft(creg);
            }
            __syncthreads();
        }
        last[us * 2 * HH + uj] = hsm[tid];

        // ---- backward LSTM: one step from zero state on x[T-1] ----
        {
            float wb0 = Wih_b[g*FF],   wb1 = Wih_b[g*FF+1], wb2 = Wih_b[g*FF+2],
                  wb3 = Wih_b[g*FF+3], wb4 = Wih_b[g*FF+4];
            float bb = bih_b[g] + bhh_b[g];
#pragma unroll
            for (int s4 = 0; s4 < 4; s4++) {
                int s = half * 4 + s4;
                const float* xt = xs + s * (TT * FF) + (TT - 1) * FF;
                float acc = bb + xt[0]*wb0 + xt[1]*wb1 + xt[2]*wb2
                               + xt[3]*wb3 + xt[4]*wb4;
                arr[s * GG + g] = (gtype == 2) ? tanhft(acc) : sigm(acc);
            }
        }
        __syncthreads();
        {
            float gi = arr[us*GG + uj], gc = arr[us*GG + 2*HH + uj];
            float go = arr[us*GG + 3*HH + uj];
            last[us * 2 * HH + HH + uj] = go * tanhft(gi * gc);   // f*c0 = 0
        }
        __syncthreads();

        // ---- fc0 + leaky ----
        {
            const float4* w4 = (const float4*)(fc0_w + uj * 2 * HH);
            const float4* l4 = (const float4*)(last + us * 2 * HH);
            float c0 = 0.f, c1 = 0.f, c2 = 0.f, c3 = 0.f;
#pragma unroll
            for (int k = 0; k < 2 * HH / 4; k++) {
                float4 wv = w4[k], lv = l4[k];
                c0 += wv.x * lv.x; c1 += wv.y * lv.y;
                c2 += wv.z * lv.z; c3 += wv.w * lv.w;
            }
            out_sm[us * HH + uj] = leaky(fc0_b[uj] + (c0 + c1) + (c2 + c3));
        }
        __syncthreads();

        // ---- epilogue scalars: 2 warps per sequence ----
        {
            int s = wid >> 1;
            if (s < ns) {
                int sg = base + g0 + s;
                const float* o = out_sm + s * HH;
                if ((wid & 1) == 0) {
#pragma unroll
                    for (int which = 0; which < 2; which++) {
                        const float* w = (which == 0) ? fc3_w : (pred_w + HH);
                        float v = o[lane] * w[lane] + o[lane + 32] * w[lane + 32];
#pragma unroll
                        for (int off = 16; off; off >>= 1)
                            v += __shfl_xor_sync(0xffffffffu, v, off);
                        if (lane == 0) {
                            if (which == 0) g_tail[sg] = leaky(v + fc3_b[0]);
                            else            g_q[sg]    = v;
                        }
                    }
                } else {
                    float v = o[lane] * pred_w[lane] + o[lane + 32] * pred_w[lane + 32];
#pragma unroll
                    for (int off = 16; off; off >>= 1)
                        v += __shfl_xor_sync(0xffffffffu, v, off);
                    if (lane == 0) g_p0[sg] = v;
                }
            }
        }
        __syncthreads();   // protect xs/arr before next group overwrites
    }

    // ===================== Grid-wide barrier ===============================
    __threadfence();                    // publish g_relw/g_tail/g_q/g_p0
    __syncthreads();
    if (tid == 0) {
        unsigned int old = atomicAdd(&g_bar_count, 1u);
        if (old == NSM - 1) {
            g_bar_count = 0;            // safe: all CTAs have arrived
            __threadfence();
            atomicAdd(&g_bar_gen, 1u);  // release
        }
    }
    // All threads spin until generation advances.
    while (*((volatile unsigned int*)&g_bar_gen) == my_gen) { }
    __threadfence();                    // acquire
    __syncthreads();

    // ====== Phase 3: masked softmax + prediction (one warp per row) ========
    // Row set == this CTA's sequence set (base..base+cnt). cnt <= 14 < 16 warps.
    if (wid < cnt) {
        int sg = base + wid;
        int b = sg >> 9, n = sg & (NN - 1);
        const float4* m4 = (const float4*)(rel_mask + (long long)n * NN);
        const float4* r4 = (const float4*)(g_relw  + (long long)n * NN);
        const float4* t4 = (const float4*)(g_tail + b * NN);
        const float4* q4 = (const float4*)(g_q    + b * NN);

        float4 l[4];
        float mx = -1e30f;
#pragma unroll
        for (int j = 0; j < 4; j++) {
            int idx = j * 32 + lane;
            float4 mv = m4[idx], rv = r4[idx], tv = t4[idx];
            l[j].x = mv.x + rv.x + tv.x;
            l[j].y = mv.y + rv.y + tv.y;
            l[j].z = mv.z + rv.z + tv.z;
            l[j].w = mv.w + rv.w + tv.w;
            mx = fmaxf(mx, fmaxf(fmaxf(l[j].x, l[j].y), fmaxf(l[j].z, l[j].w)));
        }
#pragma unroll
        for (int o = 16; o; o >>= 1) mx = fmaxf(mx, __shfl_xor_sync(0xffffffffu, mx, o));

        float se = 0.f, sq = 0.f;
#pragma unroll
        for (int j = 0; j < 4; j++) {
            int idx = j * 32 + lane;
            float4 qv = q4[idx];
            float e0 = __expf(l[j].x - mx);
            float e1 = __expf(l[j].y - mx);
            float e2 = __expf(l[j].z - mx);
            float e3 = __expf(l[j].w - mx);
            se += (e0 + e1) + (e2 + e3);
            sq += (e0 * qv.x + e1 * qv.y) + (e2 * qv.z + e3 * qv.w);
        }
#pragma unroll
        for (int o = 16; o; o >>= 1) {
            se += __shfl_xor_sync(0xffffffffu, se, o);
            sq += __shfl_xor_sync(0xffffffffu, sq, o);
        }
        if (lane == 0)
            out[sg] = leaky(g_p0[sg] + sq / se + pred_b[0]);
    }
}

// ---------------------------------------------------------------------------
extern "C" void kernel_launch(void* const* d_in, const int* in_sizes, int n_in,
                              void* d_out, int out_size) {
    const float* x      = (const float*)d_in[0];
    const float* enc    = (const float*)d_in[1];
    const float* mask   = (const float*)d_in[2];
    const float* Wih_f  = (const float*)d_in[3];
    const float* Whh_f  = (const float*)d_in[4];
    const float* bih_f  = (const float*)d_in[5];
    const float* bhh_f  = (const float*)d_in[6];
    const float* Wih_b  = (const float*)d_in[7];
    // d_in[8] (Whh_b) unused: backward LSTM runs exactly one step from zero state
    const float* bih_b  = (const float*)d_in[9];
    const float* bhh_b  = (const float*)d_in[10];
    const float* fc0_w  = (const float*)d_in[11];
    const float* fc0_b  = (const float*)d_in[12];
    const float* fc1_w  = (const float*)d_in[13];
    const float* fc1_b  = (const float*)d_in[14];
    // d_in[15..16] (fc2) unused: head term is constant over softmax axis
    const float* fc3_w  = (const float*)d_in[17];
    const float* fc3_b  = (const float*)d_in[18];
    const float* pred_w = (const float*)d_in[19];
    const float* pred_b = (const float*)d_in[20];
    float* out = (float*)d_out;

    fused_kernel<<<NSM, 512>>>(x, enc, mask, Wih_f, Whh_f, bih_f, bhh_f,
                               Wih_b, bih_b, bhh_b,
                               fc0_w, fc0_b, fc1_w, fc1_b, fc3_w, fc3_b,
                               pred_w, pred_b, out);
}

// round 6
// speedup vs baseline: 2.9048x; 1.1656x over previous
#include <cuda_runtime.h>

// Problem constants
#define BB 4
#define TT 16
#define NN 512
#define FF 5
#define HH 64
#define SS 2048           // B*N sequences
#define GG 256            // 4*H gates
#define R4 206            // RR/4 float4 per relation row
#define NSM 152           // GB300 SM count -> persistent 1 CTA/SM
#define NPAIR (NN*NN)     // 262144 relation pairs
#define NCHUNK (NPAIR/32) // 8192 32-pair chunks
#define TPC 2             // chunks per ticket

// Scratch (device globals; no allocation allowed).
// g_relw: only entries with rel_mask==0 are ever written; masked entries stay
// 0.0 (static zero-init) and are annihilated by the -1e9 mask in the softmax,
// exactly as in the reference (exp underflows to 0 in fp32). Deterministic.
__device__ float g_relw[NPAIR];
__device__ float g_tail[SS];      // leaky(out . fc3_w + fc3_b)
__device__ float g_q[SS];         // out . pred_w[64:128]
__device__ float g_p0[SS];        // out . pred_w[0:64]

// Grid-wide barrier (generation-based; replay-safe) + phase-1 work ticket.
__device__ unsigned int g_bar_count = 0;
__device__ unsigned int g_bar_gen   = 0;
__device__ unsigned int g_ticket    = 0;   // reset after barrier each launch

__device__ __forceinline__ float leaky(float v) { return v > 0.f ? v : 0.01f * v; }
// fast activations (err ~1e-6, fine at 1e-3 tolerance)
__device__ __forceinline__ float sigm(float v)   { return __fdividef(1.f, 1.f + __expf(-v)); }
__device__ __forceinline__ float tanhft(float v) { return 1.f - __fdividef(2.f, __expf(2.f * v) + 1.f); }

// packed f32x2 fma: d = a*b + d (elementwise on the two fp32 halves)
__device__ __forceinline__ void fma2(unsigned long long& d,
                                     unsigned long long a,
                                     unsigned long long b) {
    asm("fma.rn.f32x2 %0, %1, %2, %3;" : "=l"(d) : "l"(a), "l"(b), "l"(d));
}
__device__ __forceinline__ unsigned long long pack2(float lo, float hi) {
    unsigned long long r;
    asm("mov.b64 %0, {%1, %2};" : "=l"(r) : "f"(lo), "f"(hi));
    return r;
}
__device__ __forceinline__ float sum2(unsigned long long a) {
    float lo, hi;
    asm("mov.b64 {%0, %1}, %2;" : "=f"(lo), "=f"(hi) : "l"(a));
    return lo + hi;
}
#define D2L __double_as_longlong

// One 824-length dot product, 32 lanes cooperating; returns lane-0 sum.
__device__ __forceinline__ float row_dot(const float4* __restrict__ row,
                                         const float4* __restrict__ wsm,
                                         int lane) {
    float4 a0 = __ldcs(row + lane);
    float4 a1 = __ldcs(row + lane + 32);
    float4 a2 = __ldcs(row + lane + 64);
    float4 a3 = __ldcs(row + lane + 96);
    float4 a4 = __ldcs(row + lane + 128);
    float4 a5 = __ldcs(row + lane + 160);
    float4 a6 = (lane < 14) ? __ldcs(row + lane + 192)
                            : make_float4(0.f, 0.f, 0.f, 0.f);
    float s = 0.f;
    float4 w;
    w = wsm[lane];       s += a0.x*w.x + a0.y*w.y + a0.z*w.z + a0.w*w.w;
    w = wsm[lane + 32];  s += a1.x*w.x + a1.y*w.y + a1.z*w.z + a1.w*w.w;
    w = wsm[lane + 64];  s += a2.x*w.x + a2.y*w.y + a2.z*w.z + a2.w*w.w;
    w = wsm[lane + 96];  s += a3.x*w.x + a3.y*w.y + a3.z*w.z + a3.w*w.w;
    w = wsm[lane + 128]; s += a4.x*w.x + a4.y*w.y + a4.z*w.z + a4.w*w.w;
    w = wsm[lane + 160]; s += a5.x*w.x + a5.y*w.y + a5.z*w.z + a5.w*w.w;
    if (lane < 14) {
        w = wsm[lane + 192];
        s += a6.x*w.x + a6.y*w.y + a6.z*w.z + a6.w*w.w;
    }
#pragma unroll
    for (int o = 16; o; o >>= 1) s += __shfl_xor_sync(0xffffffffu, s, o);
    return s;
}

// ---------------------------------------------------------------------------
// Single persistent kernel: 152 CTAs x 512 threads (one per SM, one wave).
// Phase 1: sparse rel_weight; ticket-balanced ballot mask-scan.
// Phase 2: LSTM, all <=14 sequences of this CTA in ONE group; f32x2 FMA.
// Grid barrier, then Phase 3: masked softmax + prediction (warp per row).
// ---------------------------------------------------------------------------
__global__ __launch_bounds__(512, 1) void fused_kernel(
    const float* __restrict__ x,
    const float* __restrict__ enc,
    const float* __restrict__ rel_mask,
    const float* __restrict__ Wih_f, const float* __restrict__ Whh_f,
    const float* __restrict__ bih_f, const float* __restrict__ bhh_f,
    const float* __restrict__ Wih_b,
    const float* __restrict__ bih_b, const float* __restrict__ bhh_b,
    const float* __restrict__ fc0_w, const float* __restrict__ fc0_b,
    const float* __restrict__ fc1_w, const float* __restrict__ fc1_b,
    const float* __restrict__ fc3_w, const float* __restrict__ fc3_b,
    const float* __restrict__ pred_w, const float* __restrict__ pred_b,
    float* __restrict__ out)
{
    __shared__ float4 wsm[R4];                          // fc1 weights
    __shared__ float xs[16 * TT * FF];                  // 16 seqs x 16 x 5
    __shared__ __align__(16) float hsm[16 * HH];        // hidden states
    __shared__ float arr[16 * GG];                      // activated gates
    __shared__ __align__(16) float last[16 * 2 * HH];   // [h_fwd, h_bwd_first]
    __shared__ float out_sm[16 * HH];

    int cta = blockIdx.x;
    int tid = threadIdx.x;
    int wid = tid >> 5, lane = tid & 31;

    // Snapshot barrier generation BEFORE any arrival can happen this launch.
    unsigned int my_gen = *((volatile unsigned int*)&g_bar_gen);

    // ============ Phase 1: sparse relw, dynamic ticket + ballot ============
    const float4* w4g = (const float4*)fc1_w;
    for (int i = tid; i < R4; i += 512) wsm[i] = w4g[i];
    __syncthreads();

    {
        float fb = fc1_b[0];
        for (;;) {
            unsigned int tk;
            if (lane == 0) tk = atomicAdd(&g_ticket, 1u);
            tk = __shfl_sync(0xffffffffu, tk, 0);
            unsigned int c0 = tk * TPC;
            if (c0 >= NCHUNK) break;
#pragma unroll 1
            for (unsigned int c = c0; c < c0 + TPC && c < NCHUNK; c++) {
                int pb = c * 32;
                float mv = rel_mask[pb + lane];         // coalesced 128B load
                unsigned act = __ballot_sync(0xffffffffu, mv == 0.f);
                while (act) {
                    int b0 = __ffs(act) - 1; act &= act - 1;
                    int b1 = -1;
                    if (act) { b1 = __ffs(act) - 1; act &= act - 1; }
                    const float4* r0 = (const float4*)enc + (long long)(pb + b0) * R4;
                    float s0 = row_dot(r0, wsm, lane);
                    float s1 = 0.f;
                    if (b1 >= 0) {
                        const float4* r1 = (const float4*)enc + (long long)(pb + b1) * R4;
                        s1 = row_dot(r1, wsm, lane);
                    }
                    if (lane == 0) {
                        g_relw[pb + b0] = leaky(s0 + fb);
                        if (b1 >= 0) g_relw[pb + b1] = leaky(s1 + fb);
                    }
                }
            }
        }
    }
    __syncthreads();

    // ================= Phase 2: LSTM, one 16-seq group =====================
    int half = tid >> 8;               // gate role: which 8-seq block
    int g = tid & 255;                 // gate index 0..255
    int gtype = g >> 6;                // 0=i 1=f 2=g 3=o (per-warp uniform)
    int u  = tid & 63;                 // update/fc0 role: unit
    int s0 = tid >> 6;                 // update/fc0 role: seqs s0 and s0+8

    // Sequence range: 2048 = 152*13 + 72  -> cnt = 13 or 14 (<=16)
    int base = 13 * cta + (cta < 72 ? cta : 72);
    int cnt  = 13 + (cta < 72 ? 1 : 0);

    // Per-gate recurrent weights, packed in k-pairs for f32x2 FMA
    unsigned long long whp[HH / 2];
    {
        const double2* wg2 = (const double2*)(Whh_f + g * HH);
#pragma unroll
        for (int j = 0; j < HH / 4; j++) {
            double2 dv = wg2[j];
            whp[2*j]   = D2L(dv.x);
            whp[2*j+1] = D2L(dv.y);
        }
    }
    float wf0 = Wih_f[g*FF],   wf1 = Wih_f[g*FF+1], wf2 = Wih_f[g*FF+2],
          wf3 = Wih_f[g*FF+3], wf4 = Wih_f[g*FF+4];
    float bsum = bih_f[g] + bhh_f[g];

    // Load 16x16x5 input slices (zero-fill inactive sequences)
    for (int i = tid; i < 16 * TT * FF; i += 512) {
        float v = 0.f;
        if (i < cnt * TT * FF) {
            int s = i / (TT * FF), r = i - s * (TT * FF);
            int t = r / FF, f = r - t * FF;
            int sg = base + s;
            int b = sg >> 9, n = sg & (NN - 1);
            v = x[((b * TT + t) * NN + n) * FF + f];
        }
        xs[i] = v;
    }
    hsm[tid] = 0.f; hsm[tid + 512] = 0.f;
    float creg0 = 0.f, creg1 = 0.f;
    __syncthreads();

    // ---- forward recurrence: 16 steps x 16 sequences ----
#pragma unroll 1
    for (int t = 0; t < TT; t++) {
#pragma unroll
        for (int s8 = 0; s8 < 8; s8++) {
            int s = half * 8 + s8;
            const float* xt = xs + s * (TT * FF) + t * FF;
            float xc = bsum + xt[0]*wf0 + xt[1]*wf1 + xt[2]*wf2
                            + xt[3]*wf3 + xt[4]*wf4;
            const double2* h2 = (const double2*)(hsm + s * HH);
            unsigned long long aa = pack2(xc, 0.f), ab = 0ull;
#pragma unroll
            for (int j = 0; j < HH / 4; j++) {
                double2 hv = h2[j];
                fma2(aa, D2L(hv.x), whp[2*j]);
                fma2(ab, D2L(hv.y), whp[2*j+1]);
            }
            float av = sum2(aa) + sum2(ab);
            arr[s * GG + g] = (gtype == 2) ? tanhft(av) : sigm(av);
        }
        __syncthreads();
        {
            float gi = arr[s0*GG + u],        gf = arr[s0*GG + HH + u];
            float gc = arr[s0*GG + 2*HH + u], go = arr[s0*GG + 3*HH + u];
            creg0 = gf * creg0 + gi * gc;
            hsm[s0 * HH + u] = go * tanhft(creg0);
            int s1 = s0 + 8;
            gi = arr[s1*GG + u];        gf = arr[s1*GG + HH + u];
            gc = arr[s1*GG + 2*HH + u]; go = arr[s1*GG + 3*HH + u];
            creg1 = gf * creg1 + gi * gc;
            hsm[s1 * HH + u] = go * tanhft(creg1);
        }
        __syncthreads();
    }
    last[s0 * 2 * HH + u]       = hsm[s0 * HH + u];
    last[(s0+8) * 2 * HH + u]   = hsm[(s0+8) * HH + u];

    // ---- backward LSTM: one step from zero state on x[T-1] ----
    {
        float wb0 = Wih_b[g*FF],   wb1 = Wih_b[g*FF+1], wb2 = Wih_b[g*FF+2],
              wb3 = Wih_b[g*FF+3], wb4 = Wih_b[g*FF+4];
        float bb = bih_b[g] + bhh_b[g];
#pragma unroll
        for (int s8 = 0; s8 < 8; s8++) {
            int s = half * 8 + s8;
            const float* xt = xs + s * (TT * FF) + (TT - 1) * FF;
            float acc = bb + xt[0]*wb0 + xt[1]*wb1 + xt[2]*wb2
                           + xt[3]*wb3 + xt[4]*wb4;
            arr[s * GG + g] = (gtype == 2) ? tanhft(acc) : sigm(acc);
        }
    }
    __syncthreads();
#pragma unroll
    for (int p = 0; p < 2; p++) {
        int s = s0 + p * 8;
        float gi = arr[s*GG + u], gc = arr[s*GG + 2*HH + u];
        float go = arr[s*GG + 3*HH + u];
        last[s * 2 * HH + HH + u] = go * tanhft(gi * gc);   // f*c0 = 0
    }
    __syncthreads();

    // ---- fc0 + leaky (packed f32x2; weight row reused for both seqs) ----
    {
        const double2* w2 = (const double2*)(fc0_w + u * 2 * HH);
        const double2* la = (const double2*)(last + s0 * 2 * HH);
        const double2* lb = (const double2*)(last + (s0 + 8) * 2 * HH);
        unsigned long long a0 = 0ull, a1 = 0ull, b0 = 0ull, b1 = 0ull;
#pragma unroll
        for (int j = 0; j < 2 * HH / 4; j++) {
            double2 wv = w2[j];
            double2 va = la[j];
            double2 vb = lb[j];
            fma2(a0, D2L(va.x), D2L(wv.x));
            fma2(a1, D2L(va.y), D2L(wv.y));
            fma2(b0, D2L(vb.x), D2L(wv.x));
            fma2(b1, D2L(vb.y), D2L(wv.y));
        }
        float fb = fc0_b[u];
        out_sm[s0 * HH + u]       = leaky(fb + sum2(a0) + sum2(a1));
        out_sm[(s0 + 8) * HH + u] = leaky(fb + sum2(b0) + sum2(b1));
    }
    __syncthreads();

    // ---- epilogue scalars: one warp per sequence (3 dots fused) ----
    if (wid < cnt) {
        int sg = base + wid;
        const float* o = out_sm + wid * HH;
        float o_lo = o[lane], o_hi = o[lane + 32];
        float v0 = o_lo * fc3_w[lane]        + o_hi * fc3_w[lane + 32];
        float v1 = o_lo * pred_w[HH + lane]  + o_hi * pred_w[HH + lane + 32];
        float v2 = o_lo * pred_w[lane]       + o_hi * pred_w[lane + 32];
#pragma unroll
        for (int off = 16; off; off >>= 1) {
            v0 += __shfl_xor_sync(0xffffffffu, v0, off);
            v1 += __shfl_xor_sync(0xffffffffu, v1, off);
            v2 += __shfl_xor_sync(0xffffffffu, v2, off);
        }
        if (lane == 0) {
            g_tail[sg] = leaky(v0 + fc3_b[0]);
            g_q[sg]    = v1;
            g_p0[sg]   = v2;
        }
    }

    // ===================== Grid-wide barrier ===============================
    __threadfence();                    // publish g_relw/g_tail/g_q/g_p0
    __syncthreads();
    if (tid == 0) {
        unsigned int old = atomicAdd(&g_bar_count, 1u);
        if (old == NSM - 1) {
            g_bar_count = 0;            // all CTAs have arrived
            g_ticket = 0;               // reset work ticket for next launch
            __threadfence();
            atomicAdd(&g_bar_gen, 1u);  // release
        }
        while (*((volatile unsigned int*)&g_bar_gen) == my_gen) { }
    }
    __syncthreads();
    __threadfence();                    // acquire

    // ====== Phase 3: masked softmax + prediction (one warp per row) ========
    if (wid < cnt) {
        int sg = base + wid;
        int b = sg >> 9, n = sg & (NN - 1);
        const float4* m4 = (const float4*)(rel_mask + (long long)n * NN);
        const float4* r4 = (const float4*)(g_relw  + (long long)n * NN);
        const float4* t4 = (const float4*)(g_tail + b * NN);
        const float4* q4 = (const float4*)(g_q    + b * NN);

        float4 l[4];
        float mx = -1e30f;
#pragma unroll
        for (int j = 0; j < 4; j++) {
            int idx = j * 32 + lane;
            float4 mv = m4[idx], rv = r4[idx], tv = t4[idx];
            l[j].x = mv.x + rv.x + tv.x;
            l[j].y = mv.y + rv.y + tv.y;
            l[j].z = mv.z + rv.z + tv.z;
            l[j].w = mv.w + rv.w + tv.w;
            mx = fmaxf(mx, fmaxf(fmaxf(l[j].x, l[j].y), fmaxf(l[j].z, l[j].w)));
        }
#pragma unroll
        for (int o = 16; o; o >>= 1) mx = fmaxf(mx, __shfl_xor_sync(0xffffffffu, mx, o));

        float se = 0.f, sq = 0.f;
#pragma unroll
        for (int j = 0; j < 4; j++) {
            int idx = j * 32 + lane;
            float4 qv = q4[idx];
            float e0 = __expf(l[j].x - mx);
            float e1 = __expf(l[j].y - mx);
            float e2 = __expf(l[j].z - mx);
            float e3 = __expf(l[j].w - mx);
            se += (e0 + e1) + (e2 + e3);
            sq += (e0 * qv.x + e1 * qv.y) + (e2 * qv.z + e3 * qv.w);
        }
#pragma unroll
        for (int o = 16; o; o >>= 1) {
            se += __shfl_xor_sync(0xffffffffu, se, o);
            sq += __shfl_xor_sync(0xffffffffu, sq, o);
        }
        if (lane == 0)
            out[sg] = leaky(g_p0[sg] + sq / se + pred_b[0]);
    }
}

// ---------------------------------------------------------------------------
extern "C" void kernel_launch(void* const* d_in, const int* in_sizes, int n_in,
                              void* d_out, int out_size) {
    const float* x      = (const float*)d_in[0];
    const float* enc    = (const float*)d_in[1];
    const float* mask   = (const float*)d_in[2];
    const float* Wih_f  = (const float*)d_in[3];
    const float* Whh_f  = (const float*)d_in[4];
    const float* bih_f  = (const float*)d_in[5];
    const float* bhh_f  = (const float*)d_in[6];
    const float* Wih_b  = (const float*)d_in[7];
    // d_in[8] (Whh_b) unused: backward LSTM runs exactly one step from zero state
    const float* bih_b  = (const float*)d_in[9];
    const float* bhh_b  = (const float*)d_in[10];
    const float* fc0_w  = (const float*)d_in[11];
    const float* fc0_b  = (const float*)d_in[12];
    const float* fc1_w  = (const float*)d_in[13];
    const float* fc1_b  = (const float*)d_in[14];
    // d_in[15..16] (fc2) unused: head term is constant over softmax axis
    const float* fc3_w  = (const float*)d_in[17];
    const float* fc3_b  = (const float*)d_in[18];
    const float* pred_w = (const float*)d_in[19];
    const float* pred_b = (const float*)d_in[20];
    float* out = (float*)d_out;

    fused_kernel<<<NSM, 512>>>(x, enc, mask, Wih_f, Whh_f, bih_f, bhh_f,
                               Wih_b, bih_b, bhh_b,
                               fc0_w, fc0_b, fc1_w, fc1_b, fc3_w, fc3_b,
                               pred_w, pred_b, out);
}

// round 7
// speedup vs baseline: 3.1362x; 1.0796x over previous
#include <cuda_runtime.h>

// Problem constants
#define BB 4
#define TT 16
#define NN 512
#define FF 5
#define HH 64
#define SS 2048           // B*N sequences
#define GG 256            // 4*H gates
#define R4 206            // RR/4 float4 per relation row
#define NSM 152           // GB300 SM count -> persistent 1 CTA/SM
#define NPAIR (NN*NN)     // 262144 relation pairs
#define NCHUNK (NPAIR/32) // 8192 32-pair chunks
#define TPC 2             // chunks per ticket

// Scratch (device globals; no allocation allowed).
// g_relw: only entries with rel_mask==0 are ever written; masked entries stay
// 0.0 (static zero-init) and are annihilated by the -1e9 mask in the softmax,
// exactly as in the reference (exp underflows to 0 in fp32). Deterministic.
__device__ float g_relw[NPAIR];
__device__ float g_tail[SS];      // leaky(out . fc3_w + fc3_b)
__device__ float g_q[SS];         // out . pred_w[64:128]
__device__ float g_p0[SS];        // out . pred_w[0:64]

// Grid-wide barrier (generation-based; replay-safe) + phase-1 work ticket.
__device__ unsigned int g_bar_count = 0;
__device__ unsigned int g_bar_gen   = 0;
__device__ unsigned int g_ticket    = 0;   // reset after barrier each launch

__device__ __forceinline__ float leaky(float v) { return v > 0.f ? v : 0.01f * v; }
// fast activations (err ~1e-6, fine at 1e-3 tolerance)
__device__ __forceinline__ float sigm(float v)   { return __fdividef(1.f, 1.f + __expf(-v)); }
__device__ __forceinline__ float tanhft(float v) { return 1.f - __fdividef(2.f, __expf(2.f * v) + 1.f); }

__device__ __forceinline__ void barn(int id, int cnt) {
    asm volatile("bar.sync %0, %1;" :: "r"(id), "r"(cnt) : "memory");
}

// packed f32x2 fma: d = a*b + d (elementwise on the two fp32 halves)
__device__ __forceinline__ void fma2(unsigned long long& d,
                                     unsigned long long a,
                                     unsigned long long b) {
    asm("fma.rn.f32x2 %0, %1, %2, %3;" : "=l"(d) : "l"(a), "l"(b), "l"(d));
}
__device__ __forceinline__ unsigned long long pack2(float lo, float hi) {
    unsigned long long r;
    asm("mov.b64 %0, {%1, %2};" : "=l"(r) : "f"(lo), "f"(hi));
    return r;
}
__device__ __forceinline__ float sum2(unsigned long long a) {
    float lo, hi;
    asm("mov.b64 {%0, %1}, %2;" : "=f"(lo), "=f"(hi) : "l"(a));
    return lo + hi;
}
#define D2L __double_as_longlong

// One 824-length dot product, 32 lanes cooperating; returns lane-0 sum.
__device__ __forceinline__ float row_dot(const float4* __restrict__ row,
                                         const float4* __restrict__ wsm,
                                         int lane) {
    float4 a0 = __ldcs(row + lane);
    float4 a1 = __ldcs(row + lane + 32);
    float4 a2 = __ldcs(row + lane + 64);
    float4 a3 = __ldcs(row + lane + 96);
    float4 a4 = __ldcs(row + lane + 128);
    float4 a5 = __ldcs(row + lane + 160);
    float4 a6 = (lane < 14) ? __ldcs(row + lane + 192)
                            : make_float4(0.f, 0.f, 0.f, 0.f);
    float s = 0.f;
    float4 w;
    w = wsm[lane];       s += a0.x*w.x + a0.y*w.y + a0.z*w.z + a0.w*w.w;
    w = wsm[lane + 32];  s += a1.x*w.x + a1.y*w.y + a1.z*w.z + a1.w*w.w;
    w = wsm[lane + 64];  s += a2.x*w.x + a2.y*w.y + a2.z*w.z + a2.w*w.w;
    w = wsm[lane + 96];  s += a3.x*w.x + a3.y*w.y + a3.z*w.z + a3.w*w.w;
    w = wsm[lane + 128]; s += a4.x*w.x + a4.y*w.y + a4.z*w.z + a4.w*w.w;
    w = wsm[lane + 160]; s += a5.x*w.x + a5.y*w.y + a5.z*w.z + a5.w*w.w;
    if (lane < 14) {
        w = wsm[lane + 192];
        s += a6.x*w.x + a6.y*w.y + a6.z*w.z + a6.w*w.w;
    }
#pragma unroll
    for (int o = 16; o; o >>= 1) s += __shfl_xor_sync(0xffffffffu, s, o);
    return s;
}

// ---------------------------------------------------------------------------
// LSTM engine: 256 threads process up to 8 sequences (16 fwd steps + 1 bwd
// step + fc0 + epilogue scalars). Thread = gate (0..255); per-half named
// barrier; per-half smem buffers. f32x2-packed FMA, Whh register-resident.
// ---------------------------------------------------------------------------
__device__ __forceinline__ void lstm_group(
    int t256, int sbase, int ns,
    const float* __restrict__ x,
    const float* __restrict__ Wih_f, const float* __restrict__ Whh_f,
    const float* __restrict__ bih_f, const float* __restrict__ bhh_f,
    const float* __restrict__ Wih_b,
    const float* __restrict__ bih_b, const float* __restrict__ bhh_b,
    const float* __restrict__ fc0_w, const float* __restrict__ fc0_b,
    const float* __restrict__ fc3_w, const float* __restrict__ fc3_b,
    const float* __restrict__ pred_w,
    float* __restrict__ xs,      // [8*TT*FF]
    float* __restrict__ hsm,     // [8*HH]   (16B aligned)
    float* __restrict__ arr,     // [8*GG]
    float* __restrict__ last,    // [8*2*HH] (16B aligned)
    float* __restrict__ out_sm,  // [8*HH]
    int barid)
{
    int g = t256;                   // gate 0..255
    int gtype = g >> 6;             // 0=i 1=f 2=g 3=o (per-warp uniform)
    int u  = t256 & 63;             // unit
    int s0 = t256 >> 6;             // handles seqs s0 and s0+4
    int wl = t256 >> 5, lane = t256 & 31;

    // Per-gate recurrent weights, packed in k-pairs for f32x2 FMA
    unsigned long long whp[HH / 2];
    {
        const double2* wg2 = (const double2*)(Whh_f + g * HH);
#pragma unroll
        for (int j = 0; j < HH / 4; j++) {
            double2 dv = wg2[j];
            whp[2*j]   = D2L(dv.x);
            whp[2*j+1] = D2L(dv.y);
        }
    }
    float wf0 = Wih_f[g*FF],   wf1 = Wih_f[g*FF+1], wf2 = Wih_f[g*FF+2],
          wf3 = Wih_f[g*FF+3], wf4 = Wih_f[g*FF+4];
    float bsum = bih_f[g] + bhh_f[g];

    // Stage x: 8 x 16 x 5 (zero-fill inactive sequences)
    for (int i = t256; i < 8 * TT * FF; i += 256) {
        float v = 0.f;
        if (i < ns * TT * FF) {
            int s = i / (TT * FF), r = i - s * (TT * FF);
            int t = r / FF, f = r - t * FF;
            int sg = sbase + s;
            int b = sg >> 9, n = sg & (NN - 1);
            v = x[((b * TT + t) * NN + n) * FF + f];
        }
        xs[i] = v;
    }
    hsm[t256] = 0.f; hsm[t256 + 256] = 0.f;
    float creg0 = 0.f, creg1 = 0.f;
    barn(barid, 256);

    // ---- forward recurrence: 16 steps x 8 sequences ----
#pragma unroll 1
    for (int t = 0; t < TT; t++) {
#pragma unroll
        for (int s8 = 0; s8 < 8; s8++) {
            const float* xt = xs + s8 * (TT * FF) + t * FF;
            float xc = bsum + xt[0]*wf0 + xt[1]*wf1 + xt[2]*wf2
                            + xt[3]*wf3 + xt[4]*wf4;
            const double2* h2 = (const double2*)(hsm + s8 * HH);
            unsigned long long aa = pack2(xc, 0.f), ab = 0ull;
#pragma unroll
            for (int j = 0; j < HH / 4; j++) {
                double2 hv = h2[j];
                fma2(aa, D2L(hv.x), whp[2*j]);
                fma2(ab, D2L(hv.y), whp[2*j+1]);
            }
            float av = sum2(aa) + sum2(ab);
            arr[s8 * GG + g] = (gtype == 2) ? tanhft(av) : sigm(av);
        }
        barn(barid, 256);
        {
            float gi = arr[s0*GG + u],        gf = arr[s0*GG + HH + u];
            float gc = arr[s0*GG + 2*HH + u], go = arr[s0*GG + 3*HH + u];
            creg0 = gf * creg0 + gi * gc;
            hsm[s0 * HH + u] = go * tanhft(creg0);
            int s1 = s0 + 4;
            gi = arr[s1*GG + u];        gf = arr[s1*GG + HH + u];
            gc = arr[s1*GG + 2*HH + u]; go = arr[s1*GG + 3*HH + u];
            creg1 = gf * creg1 + gi * gc;
            hsm[s1 * HH + u] = go * tanhft(creg1);
        }
        barn(barid, 256);
    }
    last[s0 * 2 * HH + u]       = hsm[s0 * HH + u];
    last[(s0+4) * 2 * HH + u]   = hsm[(s0+4) * HH + u];

    // ---- backward LSTM: one step from zero state on x[T-1] ----
    {
        float wb0 = Wih_b[g*FF],   wb1 = Wih_b[g*FF+1], wb2 = Wih_b[g*FF+2],
              wb3 = Wih_b[g*FF+3], wb4 = Wih_b[g*FF+4];
        float bb = bih_b[g] + bhh_b[g];
#pragma unroll
        for (int s8 = 0; s8 < 8; s8++) {
            const float* xt = xs + s8 * (TT * FF) + (TT - 1) * FF;
            float acc = bb + xt[0]*wb0 + xt[1]*wb1 + xt[2]*wb2
                           + xt[3]*wb3 + xt[4]*wb4;
            arr[s8 * GG + g] = (gtype == 2) ? tanhft(acc) : sigm(acc);
        }
    }
    barn(barid, 256);
#pragma unroll
    for (int p = 0; p < 2; p++) {
        int s = s0 + p * 4;
        float gi = arr[s*GG + u], gc = arr[s*GG + 2*HH + u];
        float go = arr[s*GG + 3*HH + u];
        last[s * 2 * HH + HH + u] = go * tanhft(gi * gc);   // f*c0 = 0
    }
    barn(barid, 256);

    // ---- fc0 + leaky (packed f32x2; weight row reused for both seqs) ----
    {
        const double2* w2 = (const double2*)(fc0_w + u * 2 * HH);
        const double2* la = (const double2*)(last + s0 * 2 * HH);
        const double2* lb = (const double2*)(last + (s0 + 4) * 2 * HH);
        unsigned long long a0 = 0ull, a1 = 0ull, b0 = 0ull, b1 = 0ull;
#pragma unroll
        for (int j = 0; j < 2 * HH / 4; j++) {
            double2 wv = w2[j];
            double2 va = la[j];
            double2 vb = lb[j];
            fma2(a0, D2L(va.x), D2L(wv.x));
            fma2(a1, D2L(va.y), D2L(wv.y));
            fma2(b0, D2L(vb.x), D2L(wv.x));
            fma2(b1, D2L(vb.y), D2L(wv.y));
        }
        float fb = fc0_b[u];
        out_sm[s0 * HH + u]       = leaky(fb + sum2(a0) + sum2(a1));
        out_sm[(s0 + 4) * HH + u] = leaky(fb + sum2(b0) + sum2(b1));
    }
    barn(barid, 256);

    // ---- epilogue scalars: one warp per sequence (3 dots fused) ----
    if (wl < ns) {
        int sg = sbase + wl;
        const float* o = out_sm + wl * HH;
        float o_lo = o[lane], o_hi = o[lane + 32];
        float v0 = o_lo * fc3_w[lane]        + o_hi * fc3_w[lane + 32];
        float v1 = o_lo * pred_w[HH + lane]  + o_hi * pred_w[HH + lane + 32];
        float v2 = o_lo * pred_w[lane]       + o_hi * pred_w[lane + 32];
#pragma unroll
        for (int off = 16; off; off >>= 1) {
            v0 += __shfl_xor_sync(0xffffffffu, v0, off);
            v1 += __shfl_xor_sync(0xffffffffu, v1, off);
            v2 += __shfl_xor_sync(0xffffffffu, v2, off);
        }
        if (lane == 0) {
            g_tail[sg] = leaky(v0 + fc3_b[0]);
            g_q[sg]    = v1;
            g_p0[sg]   = v2;
        }
    }
}

// ---------------------------------------------------------------------------
// Persistent kernel: 152 CTAs x 512 threads (one per SM, one wave).
//   warps 0-7 : LSTM group A (seqs 0..7 of this CTA) immediately.
//   warps 8-15: sparse relw (ticket + ballot), THEN LSTM group B (rest).
// The relw DRAM stream overlaps group A's LDS/FMA work. Grid barrier, then
// phase 3: masked softmax + prediction (one warp per row).
// ---------------------------------------------------------------------------
__global__ __launch_bounds__(512, 1) void fused_kernel(
    const float* __restrict__ x,
    const float* __restrict__ enc,
    const float* __restrict__ rel_mask,
    const float* __restrict__ Wih_f, const float* __restrict__ Whh_f,
    const float* __restrict__ bih_f, const float* __restrict__ bhh_f,
    const float* __restrict__ Wih_b,
    const float* __restrict__ bih_b, const float* __restrict__ bhh_b,
    const float* __restrict__ fc0_w, const float* __restrict__ fc0_b,
    const float* __restrict__ fc1_w, const float* __restrict__ fc1_b,
    const float* __restrict__ fc3_w, const float* __restrict__ fc3_b,
    const float* __restrict__ pred_w, const float* __restrict__ pred_b,
    float* __restrict__ out)
{
    __shared__ float4 wsm[R4];                          // fc1 weights
    __shared__ float xsA[8 * TT * FF], xsB[8 * TT * FF];
    __shared__ __align__(16) float hsmA[8 * HH], hsmB[8 * HH];
    __shared__ float arrA[8 * GG], arrB[8 * GG];
    __shared__ __align__(16) float lastA[8 * 2 * HH], lastB[8 * 2 * HH];
    __shared__ float outA[8 * HH], outB[8 * HH];

    int cta = blockIdx.x;
    int tid = threadIdx.x;
    int wid = tid >> 5, lane = tid & 31;

    // Snapshot barrier generation BEFORE any arrival can happen this launch.
    unsigned int my_gen = *((volatile unsigned int*)&g_bar_gen);

    // Sequence range: 2048 = 152*13 + 72  -> cnt = 13 or 14
    int base = 13 * cta + (cta < 72 ? cta : 72);
    int cnt  = 13 + (cta < 72 ? 1 : 0);

    if (wid < 8) {
        // ============ Half A: LSTM group A (seqs 0..7) =====================
        lstm_group(tid, base, 8, x,
                   Wih_f, Whh_f, bih_f, bhh_f, Wih_b, bih_b, bhh_b,
                   fc0_w, fc0_b, fc3_w, fc3_b, pred_w,
                   xsA, hsmA, arrA, lastA, outA, /*barid=*/1);
    } else {
        // ============ Half B: sparse relw, then LSTM group B ===============
        int t256 = tid - 256;
        const float4* w4g = (const float4*)fc1_w;
        for (int i = t256; i < R4; i += 256) wsm[i] = w4g[i];
        barn(2, 256);

        {
            float fb = fc1_b[0];
            for (;;) {
                unsigned int tk;
                if (lane == 0) tk = atomicAdd(&g_ticket, 1u);
                tk = __shfl_sync(0xffffffffu, tk, 0);
                unsigned int c0 = tk * TPC;
                if (c0 >= NCHUNK) break;
#pragma unroll 1
                for (unsigned int c = c0; c < c0 + TPC && c < NCHUNK; c++) {
                    int pb = c * 32;
                    float mv = rel_mask[pb + lane];     // coalesced 128B load
                    unsigned act = __ballot_sync(0xffffffffu, mv == 0.f);
                    while (act) {
                        int b0 = __ffs(act) - 1; act &= act - 1;
                        int b1 = -1;
                        if (act) { b1 = __ffs(act) - 1; act &= act - 1; }
                        const float4* r0 = (const float4*)enc + (long long)(pb + b0) * R4;
                        float s0 = row_dot(r0, wsm, lane);
                        float s1 = 0.f;
                        if (b1 >= 0) {
                            const float4* r1 = (const float4*)enc + (long long)(pb + b1) * R4;
                            s1 = row_dot(r1, wsm, lane);
                        }
                        if (lane == 0) {
                            g_relw[pb + b0] = leaky(s0 + fb);
                            if (b1 >= 0) g_relw[pb + b1] = leaky(s1 + fb);
                        }
                    }
                }
            }
        }

        // LSTM group B: remaining cnt-8 sequences (5 or 6)
        lstm_group(t256, base + 8, cnt - 8, x,
                   Wih_f, Whh_f, bih_f, bhh_f, Wih_b, bih_b, bhh_b,
                   fc0_w, fc0_b, fc3_w, fc3_b, pred_w,
                   xsB, hsmB, arrB, lastB, outB, /*barid=*/2);
    }

    // ===================== Grid-wide barrier ===============================
    __threadfence();                    // publish g_relw/g_tail/g_q/g_p0
    __syncthreads();                    // join the two halves
    if (tid == 0) {
        unsigned int old = atomicAdd(&g_bar_count, 1u);
        if (old == NSM - 1) {
            g_bar_count = 0;            // all CTAs have arrived
            g_ticket = 0;               // reset work ticket for next launch
            __threadfence();
            atomicAdd(&g_bar_gen, 1u);  // release
        }
        while (*((volatile unsigned int*)&g_bar_gen) == my_gen) { }
    }
    __syncthreads();
    __threadfence();                    // acquire

    // ====== Phase 3: masked softmax + prediction (one warp per row) ========
    if (wid < cnt) {
        int sg = base + wid;
        int b = sg >> 9, n = sg & (NN - 1);
        const float4* m4 = (const float4*)(rel_mask + (long long)n * NN);
        const float4* r4 = (const float4*)(g_relw  + (long long)n * NN);
        const float4* t4 = (const float4*)(g_tail + b * NN);
        const float4* q4 = (const float4*)(g_q    + b * NN);

        float4 l[4];
        float mx = -1e30f;
#pragma unroll
        for (int j = 0; j < 4; j++) {
            int idx = j * 32 + lane;
            float4 mv = m4[idx], rv = r4[idx], tv = t4[idx];
            l[j].x = mv.x + rv.x + tv.x;
            l[j].y = mv.y + rv.y + tv.y;
            l[j].z = mv.z + rv.z + tv.z;
            l[j].w = mv.w + rv.w + tv.w;
            mx = fmaxf(mx, fmaxf(fmaxf(l[j].x, l[j].y), fmaxf(l[j].z, l[j].w)));
        }
#pragma unroll
        for (int o = 16; o; o >>= 1) mx = fmaxf(mx, __shfl_xor_sync(0xffffffffu, mx, o));

        float se = 0.f, sq = 0.f;
#pragma unroll
        for (int j = 0; j < 4; j++) {
            int idx = j * 32 + lane;
            float4 qv = q4[idx];
            float e0 = __expf(l[j].x - mx);
            float e1 = __expf(l[j].y - mx);
            float e2 = __expf(l[j].z - mx);
            float e3 = __expf(l[j].w - mx);
            se += (e0 + e1) + (e2 + e3);
            sq += (e0 * qv.x + e1 * qv.y) + (e2 * qv.z + e3 * qv.w);
        }
#pragma unroll
        for (int o = 16; o; o >>= 1) {
            se += __shfl_xor_sync(0xffffffffu, se, o);
            sq += __shfl_xor_sync(0xffffffffu, sq, o);
        }
        if (lane == 0)
            out[sg] = leaky(g_p0[sg] + sq / se + pred_b[0]);
    }
}

// ---------------------------------------------------------------------------
extern "C" void kernel_launch(void* const* d_in, const int* in_sizes, int n_in,
                              void* d_out, int out_size) {
    const float* x      = (const float*)d_in[0];
    const float* enc    = (const float*)d_in[1];
    const float* mask   = (const float*)d_in[2];
    const float* Wih_f  = (const float*)d_in[3];
    const float* Whh_f  = (const float*)d_in[4];
    const float* bih_f  = (const float*)d_in[5];
    const float* bhh_f  = (const float*)d_in[6];
    const float* Wih_b  = (const float*)d_in[7];
    // d_in[8] (Whh_b) unused: backward LSTM runs exactly one step from zero state
    const float* bih_b  = (const float*)d_in[9];
    const float* bhh_b  = (const float*)d_in[10];
    const float* fc0_w  = (const float*)d_in[11];
    const float* fc0_b  = (const float*)d_in[12];
    const float* fc1_w  = (const float*)d_in[13];
    const float* fc1_b  = (const float*)d_in[14];
    // d_in[15..16] (fc2) unused: head term is constant over softmax axis
    const float* fc3_w  = (const float*)d_in[17];
    const float* fc3_b  = (const float*)d_in[18];
    const float* pred_w = (const float*)d_in[19];
    const float* pred_b = (const float*)d_in[20];
    float* out = (float*)d_out;

    fused_kernel<<<NSM, 512>>>(x, enc, mask, Wih_f, Whh_f, bih_f, bhh_f,
                               Wih_b, bih_b, bhh_b,
                               fc0_w, fc0_b, fc1_w, fc1_b, fc3_w, fc3_b,
                               pred_w, pred_b, out);
}